// round 1
// baseline (speedup 1.0000x reference)
#include <cuda_runtime.h>
#include <math.h>

#define BATCH 4
#define SEQ   4096
#define HD    64
#define EMB   1024
#define MT    (BATCH*SEQ)
#define SD    65   // smem row stride (odd -> conflict-free strided access)

// scratch for projected q/k/v: [B*S, 64] each (4 MB each)
__device__ float g_q[MT*HD];
__device__ float g_k[MT*HD];
__device__ float g_v[MT*HD];

// ---------------------------------------------------------------------------
// QKV projection: C = X[16384,1024] @ W[1024,192]; blockIdx.y picks q/k/v col
// block tile 128(M) x 64(N), K-step 16; 256 threads, 8x4 per thread (strided)
// ---------------------------------------------------------------------------
__global__ void qkv_gemm_kernel(const float* __restrict__ x,
                                const float* __restrict__ w) {
    __shared__ float As[128][17];
    __shared__ float Bs[16][65];

    const int tid = threadIdx.x;
    const int tx  = tid & 15;
    const int ty  = tid >> 4;
    const int m0  = blockIdx.x * 128;
    const int n0  = blockIdx.y * 64;

    float acc[8][4];
#pragma unroll
    for (int i = 0; i < 8; i++)
#pragma unroll
        for (int j = 0; j < 4; j++) acc[i][j] = 0.f;

    for (int kt = 0; kt < EMB; kt += 16) {
        // A tile: 128 rows x 16 k  (512 float4, 2 per thread)
#pragma unroll
        for (int r = 0; r < 2; r++) {
            int f4  = tid + 256 * r;
            int row = f4 >> 2;
            int kc  = (f4 & 3) << 2;
            float4 v4 = *reinterpret_cast<const float4*>(
                x + (size_t)(m0 + row) * EMB + kt + kc);
            As[row][kc + 0] = v4.x; As[row][kc + 1] = v4.y;
            As[row][kc + 2] = v4.z; As[row][kc + 3] = v4.w;
        }
        // B tile: 16 k x 64 n
#pragma unroll
        for (int r = 0; r < 4; r++) {
            int f  = tid + 256 * r;
            int kk = f >> 6;
            int n  = f & 63;
            Bs[kk][n] = w[(size_t)(kt + kk) * 192 + n0 + n];
        }
        __syncthreads();
#pragma unroll
        for (int kk = 0; kk < 16; kk++) {
            float a[8], b[4];
#pragma unroll
            for (int i = 0; i < 8; i++) a[i] = As[ty + 16 * i][kk];
#pragma unroll
            for (int j = 0; j < 4; j++) b[j] = Bs[kk][tx + 16 * j];
#pragma unroll
            for (int i = 0; i < 8; i++)
#pragma unroll
                for (int j = 0; j < 4; j++) acc[i][j] += a[i] * b[j];
        }
        __syncthreads();
    }

    float* outp = (blockIdx.y == 0) ? g_q : (blockIdx.y == 1) ? g_k : g_v;
#pragma unroll
    for (int i = 0; i < 8; i++)
#pragma unroll
        for (int j = 0; j < 4; j++)
            outp[(size_t)(m0 + ty + 16 * i) * HD + tx + 16 * j] = acc[i][j];
}

// ---------------------------------------------------------------------------
// Flash attention: 64-query tile per block, stream 64-key tiles.
// 256 threads (16x16), 4x4 per thread with STRIDED mapping (row = ty+16i,
// col = tx+16j) so all inner-loop shared loads are bank-conflict-free at SD=65.
// ---------------------------------------------------------------------------
__global__ void attn_kernel(float* __restrict__ out) {
    extern __shared__ float sm[];
    float* Qs   = sm;
    float* Ks   = sm + 64 * SD;
    float* Vs   = sm + 2 * 64 * SD;
    float* Ss   = sm + 3 * 64 * SD;
    float* mrow = sm + 4 * 64 * SD;
    float* lrow = mrow + 64;
    float* arow = lrow + 64;

    const int tid = threadIdx.x;
    const int tx  = tid & 15;
    const int ty  = tid >> 4;
    const int b   = blockIdx.y;
    const int q0  = blockIdx.x * 64;

    // load + pre-scale Q tile (fold softmax scale 1/sqrt(64) into Q)
    const float* qp = g_q + ((size_t)b * SEQ + q0) * HD;
#pragma unroll
    for (int r = 0; r < 4; r++) {
        int f4  = tid + 256 * r;
        int row = f4 >> 4;
        int c   = (f4 & 15) << 2;
        float4 v4 = *reinterpret_cast<const float4*>(qp + row * HD + c);
        float* d = Qs + row * SD + c;
        d[0] = v4.x * 0.125f; d[1] = v4.y * 0.125f;
        d[2] = v4.z * 0.125f; d[3] = v4.w * 0.125f;
    }
    if (tid < 64) { mrow[tid] = -1e30f; lrow[tid] = 0.f; }

    float acc[4][4];
#pragma unroll
    for (int i = 0; i < 4; i++)
#pragma unroll
        for (int j = 0; j < 4; j++) acc[i][j] = 0.f;

    for (int kt = 0; kt < SEQ; kt += 64) {
        __syncthreads();   // prev-iter consumers of Ks/Vs/Ss done; Q/m/l visible
        const float* kp = g_k + ((size_t)b * SEQ + kt) * HD;
        const float* vp = g_v + ((size_t)b * SEQ + kt) * HD;
#pragma unroll
        for (int r = 0; r < 4; r++) {
            int f4  = tid + 256 * r;
            int row = f4 >> 4;
            int c   = (f4 & 15) << 2;
            float4 k4 = *reinterpret_cast<const float4*>(kp + row * HD + c);
            float* dk = Ks + row * SD + c;
            dk[0] = k4.x; dk[1] = k4.y; dk[2] = k4.z; dk[3] = k4.w;
            float4 v4 = *reinterpret_cast<const float4*>(vp + row * HD + c);
            float* dv = Vs + row * SD + c;
            dv[0] = v4.x; dv[1] = v4.y; dv[2] = v4.z; dv[3] = v4.w;
        }
        __syncthreads();

        // S = Q K^T  (64x64), register tiled
        float s[4][4];
#pragma unroll
        for (int i = 0; i < 4; i++)
#pragma unroll
            for (int j = 0; j < 4; j++) s[i][j] = 0.f;
#pragma unroll 8
        for (int kk = 0; kk < 64; kk++) {
            float q[4], k[4];
#pragma unroll
            for (int i = 0; i < 4; i++) q[i] = Qs[(ty + 16 * i) * SD + kk];
#pragma unroll
            for (int j = 0; j < 4; j++) k[j] = Ks[(tx + 16 * j) * SD + kk];
#pragma unroll
            for (int i = 0; i < 4; i++)
#pragma unroll
                for (int j = 0; j < 4; j++) s[i][j] += q[i] * k[j];
        }
#pragma unroll
        for (int i = 0; i < 4; i++)
#pragma unroll
            for (int j = 0; j < 4; j++)
                Ss[(ty + 16 * i) * SD + tx + 16 * j] = s[i][j];
        __syncthreads();

        // online softmax: one thread per row
        if (tid < 64) {
            float mo = mrow[tid];
            float mn = mo;
            float* sr = Ss + tid * SD;
#pragma unroll 8
            for (int j = 0; j < 64; j++) mn = fmaxf(mn, sr[j]);
            float a = __expf(mo - mn);
            float sum = 0.f;
#pragma unroll 8
            for (int j = 0; j < 64; j++) {
                float p = __expf(sr[j] - mn);
                sr[j] = p;
                sum += p;
            }
            lrow[tid] = a * lrow[tid] + sum;
            mrow[tid] = mn;
            arow[tid] = a;
        }
        __syncthreads();

        // rescale accumulators, then O += P V
        float al[4];
#pragma unroll
        for (int i = 0; i < 4; i++) al[i] = arow[ty + 16 * i];
#pragma unroll
        for (int i = 0; i < 4; i++)
#pragma unroll
            for (int j = 0; j < 4; j++) acc[i][j] *= al[i];
#pragma unroll 8
        for (int j = 0; j < 64; j++) {
            float p[4], v[4];
#pragma unroll
            for (int i = 0; i < 4; i++) p[i] = Ss[(ty + 16 * i) * SD + j];
#pragma unroll
            for (int jj = 0; jj < 4; jj++) v[jj] = Vs[j * SD + tx + 16 * jj];
#pragma unroll
            for (int i = 0; i < 4; i++)
#pragma unroll
                for (int jj = 0; jj < 4; jj++) acc[i][jj] += p[i] * v[jj];
        }
    }

    float linv[4];
#pragma unroll
    for (int i = 0; i < 4; i++) linv[i] = 1.f / lrow[ty + 16 * i];
#pragma unroll
    for (int i = 0; i < 4; i++)
#pragma unroll
        for (int j = 0; j < 4; j++)
            out[((size_t)b * SEQ + q0 + ty + 16 * i) * HD + tx + 16 * j] =
                acc[i][j] * linv[i];
}

// ---------------------------------------------------------------------------

static const int ATTN_SMEM = (4 * 64 * SD + 3 * 64) * (int)sizeof(float); // 67328 B

extern "C" void kernel_launch(void* const* d_in, const int* in_sizes, int n_in,
                              void* d_out, int out_size) {
    (void)in_sizes; (void)n_in; (void)out_size;
    const float* x = (const float*)d_in[0];   // [4,4096,1024] fp32
    const float* w = (const float*)d_in[1];   // [1024,192]   fp32
    float* out = (float*)d_out;               // [4,4096,64]  fp32

    cudaFuncSetAttribute(attn_kernel,
                         cudaFuncAttributeMaxDynamicSharedMemorySize,
                         ATTN_SMEM);

    qkv_gemm_kernel<<<dim3(MT / 128, 3), 256>>>(x, w);
    attn_kernel<<<dim3(SEQ / 64, BATCH), 256, ATTN_SMEM>>>(out);
}

// round 3
// speedup vs baseline: 1.6013x; 1.6013x over previous
#include <cuda_runtime.h>
#include <cuda_bf16.h>
#include <cstdint>
#include <math.h>

#define BATCH 4
#define SEQ   4096
#define HD    64
#define EMB   1024
#define MT    (BATCH*SEQ)

// scratch for projected q/k/v: [B*S, 64] each (4 MB each)
__device__ float g_q[MT*HD];
__device__ float g_k[MT*HD];
__device__ float g_v[MT*HD];

// ---------------------------------------------------------------------------
// mma.sync m16n8k16 bf16 -> f32  (baseline PTX, works on compute_103)
// ---------------------------------------------------------------------------
__device__ __forceinline__ void mma16816(float* d, const uint32_t* a,
                                         const uint32_t* b) {
    asm volatile(
        "mma.sync.aligned.m16n8k16.row.col.f32.bf16.bf16.f32 "
        "{%0,%1,%2,%3}, {%4,%5,%6,%7}, {%8,%9}, {%0,%1,%2,%3};"
        : "+f"(d[0]), "+f"(d[1]), "+f"(d[2]), "+f"(d[3])
        : "r"(a[0]), "r"(a[1]), "r"(a[2]), "r"(a[3]),
          "r"(b[0]), "r"(b[1]));
}

__device__ __forceinline__ uint32_t pack_bf16x2(float lo, float hi) {
    uint32_t r;
    asm("cvt.rn.bf16x2.f32 %0, %1, %2;" : "=r"(r) : "f"(hi), "f"(lo));
    return r;
}

__device__ __forceinline__ float qmax4(float v) {
    v = fmaxf(v, __shfl_xor_sync(0xffffffffu, v, 1));
    v = fmaxf(v, __shfl_xor_sync(0xffffffffu, v, 2));
    return v;
}
__device__ __forceinline__ float qsum4(float v) {
    v += __shfl_xor_sync(0xffffffffu, v, 1);
    v += __shfl_xor_sync(0xffffffffu, v, 2);
    return v;
}

// ---------------------------------------------------------------------------
// QKV projection (SIMT, known-good from round 1)
// ---------------------------------------------------------------------------
__global__ void qkv_gemm_kernel(const float* __restrict__ x,
                                const float* __restrict__ w) {
    __shared__ float As[128][17];
    __shared__ float Bs[16][65];

    const int tid = threadIdx.x;
    const int tx  = tid & 15;
    const int ty  = tid >> 4;
    const int m0  = blockIdx.x * 128;
    const int n0  = blockIdx.y * 64;

    float acc[8][4];
#pragma unroll
    for (int i = 0; i < 8; i++)
#pragma unroll
        for (int j = 0; j < 4; j++) acc[i][j] = 0.f;

    for (int kt = 0; kt < EMB; kt += 16) {
#pragma unroll
        for (int r = 0; r < 2; r++) {
            int f4  = tid + 256 * r;
            int row = f4 >> 2;
            int kc  = (f4 & 3) << 2;
            float4 v4 = *reinterpret_cast<const float4*>(
                x + (size_t)(m0 + row) * EMB + kt + kc);
            As[row][kc + 0] = v4.x; As[row][kc + 1] = v4.y;
            As[row][kc + 2] = v4.z; As[row][kc + 3] = v4.w;
        }
#pragma unroll
        for (int r = 0; r < 4; r++) {
            int f  = tid + 256 * r;
            int kk = f >> 6;
            int n  = f & 63;
            Bs[kk][n] = w[(size_t)(kt + kk) * 192 + n0 + n];
        }
        __syncthreads();
#pragma unroll
        for (int kk = 0; kk < 16; kk++) {
            float a[8], b[4];
#pragma unroll
            for (int i = 0; i < 8; i++) a[i] = As[ty + 16 * i][kk];
#pragma unroll
            for (int j = 0; j < 4; j++) b[j] = Bs[kk][tx + 16 * j];
#pragma unroll
            for (int i = 0; i < 8; i++)
#pragma unroll
                for (int j = 0; j < 4; j++) acc[i][j] += a[i] * b[j];
        }
        __syncthreads();
    }

    float* outp = (blockIdx.y == 0) ? g_q : (blockIdx.y == 1) ? g_k : g_v;
#pragma unroll
    for (int i = 0; i < 8; i++)
#pragma unroll
        for (int j = 0; j < 4; j++)
            outp[(size_t)(m0 + ty + 16 * i) * HD + tx + 16 * j] = acc[i][j];
}

// ---------------------------------------------------------------------------
// Flash attention with mma.sync bf16x3.
// 128 threads (4 warps); Q tile 64x64; each warp computes a 16-row strip.
// SMEM tiles stride 72 bf16 (144B) -> all fragment LDS are conflict-free.
// ---------------------------------------------------------------------------
#define STRD 72
// element offsets in the dynamic smem (bf16 units)
#define E_QH 0
#define E_QL (64*STRD)
#define E_KH (2*64*STRD)
#define E_KL (3*64*STRD)
#define E_VH (4*64*STRD)
#define E_VL (5*64*STRD)
#define ATTN_SMEM (6*64*STRD*2)   // 55296 bytes

__global__ __launch_bounds__(128) void attn_mma_kernel(float* __restrict__ out) {
    extern __shared__ __nv_bfloat16 sm[];
    const int tid  = threadIdx.x;
    const int lane = tid & 31;
    const int warp = tid >> 5;
    const int g    = lane >> 2;       // 0..7  (row within 8-row group / n index)
    const int tq   = lane & 3;        // 0..3  (quad lane)
    const int b    = blockIdx.y;
    const int q0   = blockIdx.x * 64;
    const int r0   = warp * 16 + g;   // S/O row (local) of c0/c1
    // r1 = r0 + 8 for c2/c3

    // ---- load + prescale + split Q tile (64 x 64) ----
    const float* qp = g_q + ((size_t)b * SEQ + q0) * HD;
#pragma unroll
    for (int r = 0; r < 8; r++) {
        int f4  = tid + 128 * r;            // 0..1023
        int row = f4 >> 4;
        int c4  = (f4 & 15) << 2;
        float4 v = *reinterpret_cast<const float4*>(qp + row * HD + c4);
        float e[4] = {v.x, v.y, v.z, v.w};
#pragma unroll
        for (int i = 0; i < 4; i++) {
            float xv = e[i] * 0.125f;       // fold 1/sqrt(64)
            __nv_bfloat16 h = __float2bfloat16(xv);
            sm[E_QH + row * STRD + c4 + i] = h;
            sm[E_QL + row * STRD + c4 + i] =
                __float2bfloat16(xv - __bfloat162float(h));
        }
    }

    float m_i[2] = {-1e30f, -1e30f};
    float l_i[2] = {0.f, 0.f};
    float oacc[8][4];
#pragma unroll
    for (int nt = 0; nt < 8; nt++)
#pragma unroll
        for (int c = 0; c < 4; c++) oacc[nt][c] = 0.f;

    for (int t = 0; t < SEQ / 64; t++) {
        __syncthreads();   // previous-iteration smem consumers done

        // ---- load + split K tile (row-major) and V tile (transposed) ----
        const float* kp = g_k + ((size_t)b * SEQ + t * 64) * HD;
        const float* vp = g_v + ((size_t)b * SEQ + t * 64) * HD;
#pragma unroll
        for (int r = 0; r < 8; r++) {
            int f4  = tid + 128 * r;
            int row = f4 >> 4;              // key index j
            int c4  = (f4 & 15) << 2;       // dim base d
            float4 kv = *reinterpret_cast<const float4*>(kp + row * HD + c4);
            float4 vv = *reinterpret_cast<const float4*>(vp + row * HD + c4);
            float ke[4] = {kv.x, kv.y, kv.z, kv.w};
            float ve[4] = {vv.x, vv.y, vv.z, vv.w};
#pragma unroll
            for (int i = 0; i < 4; i++) {
                __nv_bfloat16 h = __float2bfloat16(ke[i]);
                sm[E_KH + row * STRD + c4 + i] = h;
                sm[E_KL + row * STRD + c4 + i] =
                    __float2bfloat16(ke[i] - __bfloat162float(h));
                __nv_bfloat16 hv = __float2bfloat16(ve[i]);
                sm[E_VH + (c4 + i) * STRD + row] = hv;   // V^T
                sm[E_VL + (c4 + i) * STRD + row] =
                    __float2bfloat16(ve[i] - __bfloat162float(hv));
            }
        }
        __syncthreads();

        // ---- S = Q K^T : bf16x3, 8 n-tiles x 4 k-steps x 3 mma ----
        float sacc[8][4];
#pragma unroll
        for (int nt = 0; nt < 8; nt++)
#pragma unroll
            for (int c = 0; c < 4; c++) sacc[nt][c] = 0.f;

#pragma unroll
        for (int ks = 0; ks < 4; ks++) {
            uint32_t ah[4], al[4];
            const int ka = 16 * ks + 2 * tq;
            ah[0] = *(const uint32_t*)(sm + E_QH + r0 * STRD + ka);
            ah[1] = *(const uint32_t*)(sm + E_QH + (r0 + 8) * STRD + ka);
            ah[2] = *(const uint32_t*)(sm + E_QH + r0 * STRD + ka + 8);
            ah[3] = *(const uint32_t*)(sm + E_QH + (r0 + 8) * STRD + ka + 8);
            al[0] = *(const uint32_t*)(sm + E_QL + r0 * STRD + ka);
            al[1] = *(const uint32_t*)(sm + E_QL + (r0 + 8) * STRD + ka);
            al[2] = *(const uint32_t*)(sm + E_QL + r0 * STRD + ka + 8);
            al[3] = *(const uint32_t*)(sm + E_QL + (r0 + 8) * STRD + ka + 8);
#pragma unroll
            for (int nt = 0; nt < 8; nt++) {
                const int krow = 8 * nt + g;
                uint32_t bh[2], bl[2];
                bh[0] = *(const uint32_t*)(sm + E_KH + krow * STRD + ka);
                bh[1] = *(const uint32_t*)(sm + E_KH + krow * STRD + ka + 8);
                bl[0] = *(const uint32_t*)(sm + E_KL + krow * STRD + ka);
                bl[1] = *(const uint32_t*)(sm + E_KL + krow * STRD + ka + 8);
                mma16816(sacc[nt], ah, bh);
                mma16816(sacc[nt], ah, bl);
                mma16816(sacc[nt], al, bh);
            }
        }

        // ---- online softmax on register fragments ----
        float mx0 = sacc[0][0], mx1 = sacc[0][2];
#pragma unroll
        for (int nt = 0; nt < 8; nt++) {
            mx0 = fmaxf(mx0, fmaxf(sacc[nt][0], sacc[nt][1]));
            mx1 = fmaxf(mx1, fmaxf(sacc[nt][2], sacc[nt][3]));
        }
        mx0 = qmax4(mx0); mx1 = qmax4(mx1);
        float mn0 = fmaxf(m_i[0], mx0);
        float mn1 = fmaxf(m_i[1], mx1);
        float alpha0 = __expf(m_i[0] - mn0);
        float alpha1 = __expf(m_i[1] - mn1);
        m_i[0] = mn0; m_i[1] = mn1;

        float s0 = 0.f, s1 = 0.f;
        uint32_t ph[4][4], pl[4][4];
#pragma unroll
        for (int nt = 0; nt < 8; nt++) {
            float p0 = __expf(sacc[nt][0] - mn0);
            float p1 = __expf(sacc[nt][1] - mn0);
            float p2 = __expf(sacc[nt][2] - mn1);
            float p3 = __expf(sacc[nt][3] - mn1);
            s0 += p0 + p1;  s1 += p2 + p3;
            // bf16 hi/lo split of P, already in A-fragment layout:
            // k-step ks = nt>>1; (nt&1) selects (a0,a1) vs (a2,a3)
            float h0 = __bfloat162float(__float2bfloat16(p0));
            float h1 = __bfloat162float(__float2bfloat16(p1));
            float h2 = __bfloat162float(__float2bfloat16(p2));
            float h3 = __bfloat162float(__float2bfloat16(p3));
            int ks = nt >> 1, hi2 = (nt & 1) << 1;
            ph[ks][hi2 + 0] = pack_bf16x2(h0, h1);
            ph[ks][hi2 + 1] = pack_bf16x2(h2, h3);
            pl[ks][hi2 + 0] = pack_bf16x2(p0 - h0, p1 - h1);
            pl[ks][hi2 + 1] = pack_bf16x2(p2 - h2, p3 - h3);
        }
        s0 = qsum4(s0); s1 = qsum4(s1);
        l_i[0] = alpha0 * l_i[0] + s0;
        l_i[1] = alpha1 * l_i[1] + s1;

        // ---- rescale O, then O += P V (bf16x3, V^T in smem) ----
#pragma unroll
        for (int nt = 0; nt < 8; nt++) {
            oacc[nt][0] *= alpha0; oacc[nt][1] *= alpha0;
            oacc[nt][2] *= alpha1; oacc[nt][3] *= alpha1;
        }
#pragma unroll
        for (int ks = 0; ks < 4; ks++) {
            const int ka = 16 * ks + 2 * tq;
#pragma unroll
            for (int nt = 0; nt < 8; nt++) {
                const int drow = 8 * nt + g;
                uint32_t bh[2], bl[2];
                bh[0] = *(const uint32_t*)(sm + E_VH + drow * STRD + ka);
                bh[1] = *(const uint32_t*)(sm + E_VH + drow * STRD + ka + 8);
                bl[0] = *(const uint32_t*)(sm + E_VL + drow * STRD + ka);
                bl[1] = *(const uint32_t*)(sm + E_VL + drow * STRD + ka + 8);
                mma16816(oacc[nt], ph[ks], bh);
                mma16816(oacc[nt], ph[ks], bl);
                mma16816(oacc[nt], pl[ks], bh);
            }
        }
    }

    // ---- epilogue: normalize and store ----
    float inv0 = 1.f / l_i[0];
    float inv1 = 1.f / l_i[1];
    float* op0 = out + ((size_t)b * SEQ + q0 + r0) * HD;
    float* op1 = out + ((size_t)b * SEQ + q0 + r0 + 8) * HD;
#pragma unroll
    for (int nt = 0; nt < 8; nt++) {
        int col = 8 * nt + 2 * tq;
        float2 v0 = make_float2(oacc[nt][0] * inv0, oacc[nt][1] * inv0);
        float2 v1 = make_float2(oacc[nt][2] * inv1, oacc[nt][3] * inv1);
        *reinterpret_cast<float2*>(op0 + col) = v0;
        *reinterpret_cast<float2*>(op1 + col) = v1;
    }
}

// ---------------------------------------------------------------------------

extern "C" void kernel_launch(void* const* d_in, const int* in_sizes, int n_in,
                              void* d_out, int out_size) {
    (void)in_sizes; (void)n_in; (void)out_size;
    const float* x = (const float*)d_in[0];   // [4,4096,1024] fp32
    const float* w = (const float*)d_in[1];   // [1024,192]   fp32
    float* out = (float*)d_out;               // [4,4096,64]  fp32

    cudaFuncSetAttribute(attn_mma_kernel,
                         cudaFuncAttributeMaxDynamicSharedMemorySize,
                         ATTN_SMEM);

    qkv_gemm_kernel<<<dim3(MT / 128, 3), 256>>>(x, w);
    attn_mma_kernel<<<dim3(SEQ / 64, BATCH), 128, ATTN_SMEM>>>(out);
}

// round 4
// speedup vs baseline: 2.2522x; 1.4064x over previous
#include <cuda_runtime.h>
#include <cuda_bf16.h>
#include <cstdint>
#include <math.h>

#define BATCH 4
#define SEQ   4096
#define HD    64
#define EMB   1024
#define MT    (BATCH*SEQ)

// pre-split bf16 scratch (written by GEMM epilogue): [token][dim]
__device__ __align__(128) __nv_bfloat16 g_qh[MT*HD];
__device__ __align__(128) __nv_bfloat16 g_ql[MT*HD];
__device__ __align__(128) __nv_bfloat16 g_kh[MT*HD];
__device__ __align__(128) __nv_bfloat16 g_kl[MT*HD];
__device__ __align__(128) __nv_bfloat16 g_vh[MT*HD];
__device__ __align__(128) __nv_bfloat16 g_vl[MT*HD];

// ---------------------------------------------------------------------------
// PTX helpers (baseline PTX only — no sm_103a-gated features)
// ---------------------------------------------------------------------------
__device__ __forceinline__ uint32_t smem_to_u32(const void* p) {
    uint32_t a;
    asm("{ .reg .u64 t; cvta.to.shared.u64 t, %1; cvt.u32.u64 %0, t; }"
        : "=r"(a) : "l"(p));
    return a;
}

__device__ __forceinline__ void mma16816(float* d, const uint32_t* a,
                                         uint32_t b0, uint32_t b1) {
    asm volatile(
        "mma.sync.aligned.m16n8k16.row.col.f32.bf16.bf16.f32 "
        "{%0,%1,%2,%3}, {%4,%5,%6,%7}, {%8,%9}, {%0,%1,%2,%3};"
        : "+f"(d[0]), "+f"(d[1]), "+f"(d[2]), "+f"(d[3])
        : "r"(a[0]), "r"(a[1]), "r"(a[2]), "r"(a[3]),
          "r"(b0), "r"(b1));
}

#define LDSM_X4(r, addr) \
    asm volatile("ldmatrix.sync.aligned.m8n8.x4.shared.b16 {%0,%1,%2,%3}, [%4];" \
        : "=r"((r)[0]), "=r"((r)[1]), "=r"((r)[2]), "=r"((r)[3]) : "r"(addr))
#define LDSM_X4_T(r, addr) \
    asm volatile("ldmatrix.sync.aligned.m8n8.x4.trans.shared.b16 {%0,%1,%2,%3}, [%4];" \
        : "=r"((r)[0]), "=r"((r)[1]), "=r"((r)[2]), "=r"((r)[3]) : "r"(addr))

#define CP_ASYNC16(saddr, gptr) \
    asm volatile("cp.async.cg.shared.global [%0], [%1], 16;" \
        :: "r"(saddr), "l"(__cvta_generic_to_global(gptr)) : "memory")
#define CP_COMMIT() asm volatile("cp.async.commit_group;" ::: "memory")

__device__ __forceinline__ uint32_t pack_bf16x2(float lo, float hi) {
    uint32_t r;
    asm("cvt.rn.bf16x2.f32 %0, %1, %2;" : "=r"(r) : "f"(hi), "f"(lo));
    return r;
}
__device__ __forceinline__ float qmax4(float v) {
    v = fmaxf(v, __shfl_xor_sync(0xffffffffu, v, 1));
    v = fmaxf(v, __shfl_xor_sync(0xffffffffu, v, 2));
    return v;
}
__device__ __forceinline__ float qsum4(float v) {
    v += __shfl_xor_sync(0xffffffffu, v, 1);
    v += __shfl_xor_sync(0xffffffffu, v, 2);
    return v;
}

// ---------------------------------------------------------------------------
// QKV projection (SIMT core, known-good) — epilogue writes pre-split bf16.
// q gets the 1/sqrt(64) scale folded in.
// ---------------------------------------------------------------------------
__global__ void qkv_gemm_kernel(const float* __restrict__ x,
                                const float* __restrict__ w) {
    __shared__ float As[128][17];
    __shared__ float Bs[16][65];

    const int tid = threadIdx.x;
    const int tx  = tid & 15;
    const int ty  = tid >> 4;
    const int m0  = blockIdx.x * 128;
    const int n0  = blockIdx.y * 64;

    float acc[8][4];
#pragma unroll
    for (int i = 0; i < 8; i++)
#pragma unroll
        for (int j = 0; j < 4; j++) acc[i][j] = 0.f;

    for (int kt = 0; kt < EMB; kt += 16) {
#pragma unroll
        for (int r = 0; r < 2; r++) {
            int f4  = tid + 256 * r;
            int row = f4 >> 2;
            int kc  = (f4 & 3) << 2;
            float4 v4 = *reinterpret_cast<const float4*>(
                x + (size_t)(m0 + row) * EMB + kt + kc);
            As[row][kc + 0] = v4.x; As[row][kc + 1] = v4.y;
            As[row][kc + 2] = v4.z; As[row][kc + 3] = v4.w;
        }
#pragma unroll
        for (int r = 0; r < 4; r++) {
            int f  = tid + 256 * r;
            int kk = f >> 6;
            int n  = f & 63;
            Bs[kk][n] = w[(size_t)(kt + kk) * 192 + n0 + n];
        }
        __syncthreads();
#pragma unroll
        for (int kk = 0; kk < 16; kk++) {
            float a[8], b[4];
#pragma unroll
            for (int i = 0; i < 8; i++) a[i] = As[ty + 16 * i][kk];
#pragma unroll
            for (int j = 0; j < 4; j++) b[j] = Bs[kk][tx + 16 * j];
#pragma unroll
            for (int i = 0; i < 8; i++)
#pragma unroll
                for (int j = 0; j < 4; j++) acc[i][j] += a[i] * b[j];
        }
        __syncthreads();
    }

    __nv_bfloat16* oh;
    __nv_bfloat16* ol;
    float scale = 1.f;
    if (blockIdx.y == 0)      { oh = g_qh; ol = g_ql; scale = 0.125f; }
    else if (blockIdx.y == 1) { oh = g_kh; ol = g_kl; }
    else                      { oh = g_vh; ol = g_vl; }

#pragma unroll
    for (int i = 0; i < 8; i++)
#pragma unroll
        for (int j = 0; j < 4; j++) {
            float v = acc[i][j] * scale;
            __nv_bfloat16 h = __float2bfloat16(v);
            size_t idx = (size_t)(m0 + ty + 16 * i) * HD + tx + 16 * j;
            oh[idx] = h;
            ol[idx] = __float2bfloat16(v - __bfloat162float(h));
        }
}

// ---------------------------------------------------------------------------
// Flash attention: mma.sync bf16x3, ldmatrix fragments, cp.async 2-stage pipe.
// 128 threads (4 warps); Q tile 64 rows; each warp owns a 16-row strip.
// ---------------------------------------------------------------------------
#define STRD 72                       // bf16 elements per smem row (144 B)
#define TILE_ELS (64*STRD)            // one 64x64 tile with padding
// element offsets within dynamic smem
#define E_QH 0
#define E_QL TILE_ELS
#define E_STG(s) (2*TILE_ELS + (s)*4*TILE_ELS)
#define E_KH(s) (E_STG(s))
#define E_KL(s) (E_STG(s) + TILE_ELS)
#define E_VH(s) (E_STG(s) + 2*TILE_ELS)
#define E_VL(s) (E_STG(s) + 3*TILE_ELS)
#define ATTN_SMEM ((2 + 8) * TILE_ELS * 2)   // 92160 bytes

// issue cp.async copies of one 64x64 bf16 tile (global row-major, 64 els/row)
__device__ __forceinline__ void tile_copy_async(
    uint32_t su, int eoff, const __nv_bfloat16* src, int tid) {
#pragma unroll
    for (int r = 0; r < 4; r++) {
        int c   = tid + 128 * r;          // 0..511 chunks of 16B
        int row = c >> 3;
        int ch  = c & 7;
        uint32_t sa = su + (uint32_t)(eoff + row * STRD + ch * 8) * 2;
        CP_ASYNC16(sa, src + row * HD + ch * 8);
    }
}

__global__ __launch_bounds__(128) void attn_mma_kernel(float* __restrict__ out) {
    extern __shared__ __nv_bfloat16 sm[];
    const uint32_t su = smem_to_u32(sm);
    const int tid  = threadIdx.x;
    const int lane = tid & 31;
    const int warp = tid >> 5;
    const int g    = lane >> 2;
    const int tq   = lane & 3;
    const int lrow = lane & 15;       // ldmatrix row-within-16
    const int lsel = lane >> 4;       // ldmatrix 8-col block select
    const int b    = blockIdx.y;
    const int q0   = blockIdx.x * 64;
    const int r0   = warp * 16 + g;

    const size_t tokbase = (size_t)b * SEQ;

    // ---- copy Q tile (already scaled + split) ----
    {
        const __nv_bfloat16* qh = g_qh + (tokbase + q0) * HD;
        const __nv_bfloat16* ql = g_ql + (tokbase + q0) * HD;
#pragma unroll
        for (int r = 0; r < 8; r++) {
            int c   = tid + 128 * (r & 3);
            int row = c >> 3;
            int ch  = c & 7;
            const __nv_bfloat16* src = (r < 4 ? qh : ql) + row * HD + ch * 8;
            uint4 v = *reinterpret_cast<const uint4*>(src);
            *reinterpret_cast<uint4*>(sm + (r < 4 ? E_QH : E_QL) +
                                      row * STRD + ch * 8) = v;
        }
    }

    // ---- prologue: stage 0 of K/V pipeline ----
    tile_copy_async(su, E_KH(0), g_kh + tokbase * HD, tid);
    tile_copy_async(su, E_KL(0), g_kl + tokbase * HD, tid);
    tile_copy_async(su, E_VH(0), g_vh + tokbase * HD, tid);
    tile_copy_async(su, E_VL(0), g_vl + tokbase * HD, tid);
    CP_COMMIT();

    float m_i[2] = {-1e30f, -1e30f};
    float l_i[2] = {0.f, 0.f};
    float oacc[8][4];
#pragma unroll
    for (int nt = 0; nt < 8; nt++)
#pragma unroll
        for (int c = 0; c < 4; c++) oacc[nt][c] = 0.f;

#pragma unroll 1
    for (int t = 0; t < SEQ / 64; t++) {
        const int st = t & 1;
        // issue next tile into the other stage, then wait for tile t
        if (t + 1 < SEQ / 64) {
            const size_t nb = (tokbase + (t + 1) * 64) * HD;
            const int ns = (t + 1) & 1;
            tile_copy_async(su, E_KH(ns), g_kh + nb, tid);
            tile_copy_async(su, E_KL(ns), g_kl + nb, tid);
            tile_copy_async(su, E_VH(ns), g_vh + nb, tid);
            tile_copy_async(su, E_VL(ns), g_vl + nb, tid);
            CP_COMMIT();
            asm volatile("cp.async.wait_group 1;" ::: "memory");
        } else {
            asm volatile("cp.async.wait_group 0;" ::: "memory");
        }
        __syncthreads();

        // ---- S = Q K^T (bf16x3) ----
        float sacc[8][4];
#pragma unroll
        for (int nt = 0; nt < 8; nt++)
#pragma unroll
            for (int c = 0; c < 4; c++) sacc[nt][c] = 0.f;

#pragma unroll
        for (int ks = 0; ks < 4; ks++) {
            const int acol = 16 * ks + 8 * lsel;
            uint32_t ah[4], al[4];
            LDSM_X4(ah, su + (uint32_t)(E_QH + (warp * 16 + lrow) * STRD + acol) * 2);
            LDSM_X4(al, su + (uint32_t)(E_QL + (warp * 16 + lrow) * STRD + acol) * 2);
#pragma unroll
            for (int np = 0; np < 4; np++) {
                uint32_t bh[4], bl[4];
                const int krow = np * 16 + lrow;
                LDSM_X4(bh, su + (uint32_t)(E_KH(st) + krow * STRD + acol) * 2);
                LDSM_X4(bl, su + (uint32_t)(E_KL(st) + krow * STRD + acol) * 2);
                mma16816(sacc[2 * np],     ah, bh[0], bh[2]);
                mma16816(sacc[2 * np],     ah, bl[0], bl[2]);
                mma16816(sacc[2 * np],     al, bh[0], bh[2]);
                mma16816(sacc[2 * np + 1], ah, bh[1], bh[3]);
                mma16816(sacc[2 * np + 1], ah, bl[1], bl[3]);
                mma16816(sacc[2 * np + 1], al, bh[1], bh[3]);
            }
        }

        // ---- online softmax on register fragments ----
        float mx0 = sacc[0][0], mx1 = sacc[0][2];
#pragma unroll
        for (int nt = 0; nt < 8; nt++) {
            mx0 = fmaxf(mx0, fmaxf(sacc[nt][0], sacc[nt][1]));
            mx1 = fmaxf(mx1, fmaxf(sacc[nt][2], sacc[nt][3]));
        }
        mx0 = qmax4(mx0); mx1 = qmax4(mx1);
        float mn0 = fmaxf(m_i[0], mx0);
        float mn1 = fmaxf(m_i[1], mx1);
        float alpha0 = __expf(m_i[0] - mn0);
        float alpha1 = __expf(m_i[1] - mn1);
        m_i[0] = mn0; m_i[1] = mn1;

        float s0 = 0.f, s1 = 0.f;
        uint32_t ph[4][4], pl[4][4];
#pragma unroll
        for (int nt = 0; nt < 8; nt++) {
            float p0 = __expf(sacc[nt][0] - mn0);
            float p1 = __expf(sacc[nt][1] - mn0);
            float p2 = __expf(sacc[nt][2] - mn1);
            float p3 = __expf(sacc[nt][3] - mn1);
            s0 += p0 + p1;  s1 += p2 + p3;
            float h0 = __bfloat162float(__float2bfloat16(p0));
            float h1 = __bfloat162float(__float2bfloat16(p1));
            float h2 = __bfloat162float(__float2bfloat16(p2));
            float h3 = __bfloat162float(__float2bfloat16(p3));
            int ks = nt >> 1, hi2 = (nt & 1) << 1;
            ph[ks][hi2 + 0] = pack_bf16x2(h0, h1);
            ph[ks][hi2 + 1] = pack_bf16x2(h2, h3);
            pl[ks][hi2 + 0] = pack_bf16x2(p0 - h0, p1 - h1);
            pl[ks][hi2 + 1] = pack_bf16x2(p2 - h2, p3 - h3);
        }
        s0 = qsum4(s0); s1 = qsum4(s1);
        l_i[0] = alpha0 * l_i[0] + s0;
        l_i[1] = alpha1 * l_i[1] + s1;

        // ---- rescale O, then O += P V (V row-major via ldmatrix.trans) ----
#pragma unroll
        for (int nt = 0; nt < 8; nt++) {
            oacc[nt][0] *= alpha0; oacc[nt][1] *= alpha0;
            oacc[nt][2] *= alpha1; oacc[nt][3] *= alpha1;
        }
#pragma unroll
        for (int ks = 0; ks < 4; ks++) {
            const int vrow = 16 * ks + lrow;
#pragma unroll
            for (int np = 0; np < 4; np++) {
                uint32_t bh[4], bl[4];
                const int vcol = 16 * np + 8 * lsel;
                LDSM_X4_T(bh, su + (uint32_t)(E_VH(st) + vrow * STRD + vcol) * 2);
                LDSM_X4_T(bl, su + (uint32_t)(E_VL(st) + vrow * STRD + vcol) * 2);
                mma16816(oacc[2 * np],     ph[ks], bh[0], bh[1]);
                mma16816(oacc[2 * np],     ph[ks], bl[0], bl[1]);
                mma16816(oacc[2 * np],     pl[ks], bh[0], bh[1]);
                mma16816(oacc[2 * np + 1], ph[ks], bh[2], bh[3]);
                mma16816(oacc[2 * np + 1], ph[ks], bl[2], bl[3]);
                mma16816(oacc[2 * np + 1], pl[ks], bh[2], bh[3]);
            }
        }
        __syncthreads();   // stage st free for reuse by the t+2 issue
    }

    // ---- epilogue: normalize and store ----
    float inv0 = 1.f / l_i[0];
    float inv1 = 1.f / l_i[1];
    float* op0 = out + (tokbase + q0 + r0) * HD;
    float* op1 = out + (tokbase + q0 + r0 + 8) * HD;
#pragma unroll
    for (int nt = 0; nt < 8; nt++) {
        int col = 8 * nt + 2 * tq;
        *reinterpret_cast<float2*>(op0 + col) =
            make_float2(oacc[nt][0] * inv0, oacc[nt][1] * inv0);
        *reinterpret_cast<float2*>(op1 + col) =
            make_float2(oacc[nt][2] * inv1, oacc[nt][3] * inv1);
    }
}

// ---------------------------------------------------------------------------

extern "C" void kernel_launch(void* const* d_in, const int* in_sizes, int n_in,
                              void* d_out, int out_size) {
    (void)in_sizes; (void)n_in; (void)out_size;
    const float* x = (const float*)d_in[0];   // [4,4096,1024] fp32
    const float* w = (const float*)d_in[1];   // [1024,192]   fp32
    float* out = (float*)d_out;               // [4,4096,64]  fp32

    cudaFuncSetAttribute(attn_mma_kernel,
                         cudaFuncAttributeMaxDynamicSharedMemorySize,
                         ATTN_SMEM);

    qkv_gemm_kernel<<<dim3(MT / 128, 3), 256>>>(x, w);
    attn_mma_kernel<<<dim3(SEQ / 64, BATCH), 128, ATTN_SMEM>>>(out);
}

// round 5
// speedup vs baseline: 3.3655x; 1.4943x over previous
#include <cuda_runtime.h>
#include <cuda_bf16.h>
#include <cstdint>
#include <math.h>

#define BATCH 4
#define SEQ   4096
#define HD    64
#define EMB   1024
#define MT    (BATCH*SEQ)

// pre-split bf16 scratch (written by GEMM epilogue): [token][dim]
__device__ __align__(128) __nv_bfloat16 g_qh[MT*HD];
__device__ __align__(128) __nv_bfloat16 g_ql[MT*HD];
__device__ __align__(128) __nv_bfloat16 g_kh[MT*HD];
__device__ __align__(128) __nv_bfloat16 g_kl[MT*HD];
__device__ __align__(128) __nv_bfloat16 g_vh[MT*HD];
__device__ __align__(128) __nv_bfloat16 g_vl[MT*HD];

// ---------------------------------------------------------------------------
// PTX helpers (baseline PTX only — no sm_103a-gated features)
// ---------------------------------------------------------------------------
__device__ __forceinline__ uint32_t smem_to_u32(const void* p) {
    uint32_t a;
    asm("{ .reg .u64 t; cvta.to.shared.u64 t, %1; cvt.u32.u64 %0, t; }"
        : "=r"(a) : "l"(p));
    return a;
}

__device__ __forceinline__ void mma16816(float* d, const uint32_t* a,
                                         uint32_t b0, uint32_t b1) {
    asm volatile(
        "mma.sync.aligned.m16n8k16.row.col.f32.bf16.bf16.f32 "
        "{%0,%1,%2,%3}, {%4,%5,%6,%7}, {%8,%9}, {%0,%1,%2,%3};"
        : "+f"(d[0]), "+f"(d[1]), "+f"(d[2]), "+f"(d[3])
        : "r"(a[0]), "r"(a[1]), "r"(a[2]), "r"(a[3]),
          "r"(b0), "r"(b1));
}

#define LDSM_X4(r, addr) \
    asm volatile("ldmatrix.sync.aligned.m8n8.x4.shared.b16 {%0,%1,%2,%3}, [%4];" \
        : "=r"((r)[0]), "=r"((r)[1]), "=r"((r)[2]), "=r"((r)[3]) : "r"(addr))
#define LDSM_X4_T(r, addr) \
    asm volatile("ldmatrix.sync.aligned.m8n8.x4.trans.shared.b16 {%0,%1,%2,%3}, [%4];" \
        : "=r"((r)[0]), "=r"((r)[1]), "=r"((r)[2]), "=r"((r)[3]) : "r"(addr))

#define CP_ASYNC16(saddr, gptr) \
    asm volatile("cp.async.cg.shared.global [%0], [%1], 16;" \
        :: "r"(saddr), "l"(__cvta_generic_to_global(gptr)) : "memory")
#define CP_COMMIT() asm volatile("cp.async.commit_group;" ::: "memory")

__device__ __forceinline__ uint32_t pack_bf16x2(float lo, float hi) {
    uint32_t r;
    asm("cvt.rn.bf16x2.f32 %0, %1, %2;" : "=r"(r) : "f"(hi), "f"(lo));
    return r;
}
// split a pair of fp32 into packed bf16 hi + packed bf16 lo
__device__ __forceinline__ void split2(float e0, float e1,
                                       uint32_t& hi, uint32_t& lo) {
    __nv_bfloat16 h0 = __float2bfloat16(e0);
    __nv_bfloat16 h1 = __float2bfloat16(e1);
    hi = (uint32_t)__bfloat16_as_ushort(h0) |
         ((uint32_t)__bfloat16_as_ushort(h1) << 16);
    lo = pack_bf16x2(e0 - __bfloat162float(h0), e1 - __bfloat162float(h1));
}
__device__ __forceinline__ float qmax4(float v) {
    v = fmaxf(v, __shfl_xor_sync(0xffffffffu, v, 1));
    v = fmaxf(v, __shfl_xor_sync(0xffffffffu, v, 2));
    return v;
}
__device__ __forceinline__ float qsum4(float v) {
    v += __shfl_xor_sync(0xffffffffu, v, 1);
    v += __shfl_xor_sync(0xffffffffu, v, 2);
    return v;
}

// ---------------------------------------------------------------------------
// QKV projection, tensorized (bf16x3 via mma.sync).
// CTA tile 128M x 64N, K-tile 64, 256 threads (8 warps, 16 rows each).
// X fp32 is split hi/lo during the smem store; W likewise.
// ---------------------------------------------------------------------------
#define GSTR 72
// bf16-element offsets in gemm smem
#define GE_XH 0
#define GE_XL (128*GSTR)
#define GE_WH (2*128*GSTR)
#define GE_WL (GE_WH + 64*GSTR)
#define GEMM_SMEM ((2*128 + 2*64) * GSTR * 2)   // 55296 B

__global__ __launch_bounds__(256, 2) void qkv_mma_kernel(
        const float* __restrict__ x, const float* __restrict__ w) {
    extern __shared__ __nv_bfloat16 gsm[];
    const uint32_t su = smem_to_u32(gsm);
    const int tid  = threadIdx.x;
    const int lane = tid & 31;
    const int warp = tid >> 5;
    const int g    = lane >> 2;
    const int tq   = lane & 3;
    const int lrow = lane & 15;
    const int lsel = lane >> 4;
    const int m0   = blockIdx.x * 128;
    const int n0   = blockIdx.y * 64;

    float acc[8][4];
#pragma unroll
    for (int nt = 0; nt < 8; nt++)
#pragma unroll
        for (int c = 0; c < 4; c++) acc[nt][c] = 0.f;

    float4 xr[8], wr[4];
    // prefetch k-tile 0
#pragma unroll
    for (int r = 0; r < 8; r++) {
        int f4 = tid + 256 * r, row = f4 >> 4, c4 = (f4 & 15) << 2;
        xr[r] = *reinterpret_cast<const float4*>(x + (size_t)(m0 + row) * EMB + c4);
    }
#pragma unroll
    for (int r = 0; r < 4; r++) {
        int f4 = tid + 256 * r, row = f4 >> 4, c4 = (f4 & 15) << 2;
        wr[r] = *reinterpret_cast<const float4*>(w + (size_t)row * 192 + n0 + c4);
    }

#pragma unroll 1
    for (int kt = 0; kt < EMB / 64; kt++) {
        // ---- convert + store split tiles ----
#pragma unroll
        for (int r = 0; r < 8; r++) {
            int f4 = tid + 256 * r, row = f4 >> 4, c = (f4 & 15) << 2;
            uint32_t h0, l0, h1, l1;
            split2(xr[r].x, xr[r].y, h0, l0);
            split2(xr[r].z, xr[r].w, h1, l1);
            *reinterpret_cast<uint2*>(gsm + GE_XH + row * GSTR + c) = make_uint2(h0, h1);
            *reinterpret_cast<uint2*>(gsm + GE_XL + row * GSTR + c) = make_uint2(l0, l1);
        }
#pragma unroll
        for (int r = 0; r < 4; r++) {
            int f4 = tid + 256 * r, row = f4 >> 4, c = (f4 & 15) << 2;
            uint32_t h0, l0, h1, l1;
            split2(wr[r].x, wr[r].y, h0, l0);
            split2(wr[r].z, wr[r].w, h1, l1);
            *reinterpret_cast<uint2*>(gsm + GE_WH + row * GSTR + c) = make_uint2(h0, h1);
            *reinterpret_cast<uint2*>(gsm + GE_WL + row * GSTR + c) = make_uint2(l0, l1);
        }
        __syncthreads();

        // ---- prefetch next k-tile into registers (hidden under mma) ----
        if (kt + 1 < EMB / 64) {
            const int kb = (kt + 1) * 64;
#pragma unroll
            for (int r = 0; r < 8; r++) {
                int f4 = tid + 256 * r, row = f4 >> 4, c4 = (f4 & 15) << 2;
                xr[r] = *reinterpret_cast<const float4*>(
                    x + (size_t)(m0 + row) * EMB + kb + c4);
            }
#pragma unroll
            for (int r = 0; r < 4; r++) {
                int f4 = tid + 256 * r, row = f4 >> 4, c4 = (f4 & 15) << 2;
                wr[r] = *reinterpret_cast<const float4*>(
                    w + (size_t)(kb + row) * 192 + n0 + c4);
            }
        }

        // ---- mma over this 64-k tile: 4 ksteps x 8 ntiles x 3 ----
#pragma unroll
        for (int ks = 0; ks < 4; ks++) {
            const int acol = 16 * ks + 8 * lsel;
            uint32_t ah[4], al[4];
            LDSM_X4(ah, su + (uint32_t)(GE_XH + (warp * 16 + lrow) * GSTR + acol) * 2);
            LDSM_X4(al, su + (uint32_t)(GE_XL + (warp * 16 + lrow) * GSTR + acol) * 2);
            const int wrow = 16 * ks + lrow;
#pragma unroll
            for (int np = 0; np < 4; np++) {
                uint32_t bh[4], bl[4];
                const int wcol = 16 * np + 8 * lsel;
                LDSM_X4_T(bh, su + (uint32_t)(GE_WH + wrow * GSTR + wcol) * 2);
                LDSM_X4_T(bl, su + (uint32_t)(GE_WL + wrow * GSTR + wcol) * 2);
                mma16816(acc[2 * np],     ah, bh[0], bh[1]);
                mma16816(acc[2 * np],     ah, bl[0], bl[1]);
                mma16816(acc[2 * np],     al, bh[0], bh[1]);
                mma16816(acc[2 * np + 1], ah, bh[2], bh[3]);
                mma16816(acc[2 * np + 1], ah, bl[2], bl[3]);
                mma16816(acc[2 * np + 1], al, bh[2], bh[3]);
            }
        }
        __syncthreads();
    }

    // ---- epilogue: scale (q only), split, store bf16 hi/lo ----
    __nv_bfloat16 *oh, *ol;
    float scale = 1.f;
    if (blockIdx.y == 0)      { oh = g_qh; ol = g_ql; scale = 0.125f; }
    else if (blockIdx.y == 1) { oh = g_kh; ol = g_kl; }
    else                      { oh = g_vh; ol = g_vl; }

    const int ra = m0 + warp * 16 + g;
#pragma unroll
    for (int nt = 0; nt < 8; nt++) {
        const int c = 8 * nt + 2 * tq;
        uint32_t hi, lo;
        split2(acc[nt][0] * scale, acc[nt][1] * scale, hi, lo);
        *reinterpret_cast<uint32_t*>(oh + (size_t)ra * HD + c) = hi;
        *reinterpret_cast<uint32_t*>(ol + (size_t)ra * HD + c) = lo;
        split2(acc[nt][2] * scale, acc[nt][3] * scale, hi, lo);
        *reinterpret_cast<uint32_t*>(oh + (size_t)(ra + 8) * HD + c) = hi;
        *reinterpret_cast<uint32_t*>(ol + (size_t)(ra + 8) * HD + c) = lo;
    }
}

// ---------------------------------------------------------------------------
// Flash attention: mma.sync bf16x3, ldmatrix fragments, cp.async 2-stage pipe.
// (unchanged from round 4 — 192us, 44% tensor)
// ---------------------------------------------------------------------------
#define STRD 72
#define TILE_ELS (64*STRD)
#define E_QH 0
#define E_QL TILE_ELS
#define E_STG(s) (2*TILE_ELS + (s)*4*TILE_ELS)
#define E_KH(s) (E_STG(s))
#define E_KL(s) (E_STG(s) + TILE_ELS)
#define E_VH(s) (E_STG(s) + 2*TILE_ELS)
#define E_VL(s) (E_STG(s) + 3*TILE_ELS)
#define ATTN_SMEM ((2 + 8) * TILE_ELS * 2)   // 92160 bytes

__device__ __forceinline__ void tile_copy_async(
    uint32_t su, int eoff, const __nv_bfloat16* src, int tid) {
#pragma unroll
    for (int r = 0; r < 4; r++) {
        int c   = tid + 128 * r;
        int row = c >> 3;
        int ch  = c & 7;
        uint32_t sa = su + (uint32_t)(eoff + row * STRD + ch * 8) * 2;
        CP_ASYNC16(sa, src + row * HD + ch * 8);
    }
}

__global__ __launch_bounds__(128) void attn_mma_kernel(float* __restrict__ out) {
    extern __shared__ __nv_bfloat16 sm[];
    const uint32_t su = smem_to_u32(sm);
    const int tid  = threadIdx.x;
    const int lane = tid & 31;
    const int warp = tid >> 5;
    const int g    = lane >> 2;
    const int tq   = lane & 3;
    const int lrow = lane & 15;
    const int lsel = lane >> 4;
    const int b    = blockIdx.y;
    const int q0   = blockIdx.x * 64;
    const int r0   = warp * 16 + g;

    const size_t tokbase = (size_t)b * SEQ;

    {
        const __nv_bfloat16* qh = g_qh + (tokbase + q0) * HD;
        const __nv_bfloat16* ql = g_ql + (tokbase + q0) * HD;
#pragma unroll
        for (int r = 0; r < 8; r++) {
            int c   = tid + 128 * (r & 3);
            int row = c >> 3;
            int ch  = c & 7;
            const __nv_bfloat16* src = (r < 4 ? qh : ql) + row * HD + ch * 8;
            uint4 v = *reinterpret_cast<const uint4*>(src);
            *reinterpret_cast<uint4*>(sm + (r < 4 ? E_QH : E_QL) +
                                      row * STRD + ch * 8) = v;
        }
    }

    tile_copy_async(su, E_KH(0), g_kh + tokbase * HD, tid);
    tile_copy_async(su, E_KL(0), g_kl + tokbase * HD, tid);
    tile_copy_async(su, E_VH(0), g_vh + tokbase * HD, tid);
    tile_copy_async(su, E_VL(0), g_vl + tokbase * HD, tid);
    CP_COMMIT();

    float m_i[2] = {-1e30f, -1e30f};
    float l_i[2] = {0.f, 0.f};
    float oacc[8][4];
#pragma unroll
    for (int nt = 0; nt < 8; nt++)
#pragma unroll
        for (int c = 0; c < 4; c++) oacc[nt][c] = 0.f;

#pragma unroll 1
    for (int t = 0; t < SEQ / 64; t++) {
        const int st = t & 1;
        if (t + 1 < SEQ / 64) {
            const size_t nb = (tokbase + (t + 1) * 64) * HD;
            const int ns = (t + 1) & 1;
            tile_copy_async(su, E_KH(ns), g_kh + nb, tid);
            tile_copy_async(su, E_KL(ns), g_kl + nb, tid);
            tile_copy_async(su, E_VH(ns), g_vh + nb, tid);
            tile_copy_async(su, E_VL(ns), g_vl + nb, tid);
            CP_COMMIT();
            asm volatile("cp.async.wait_group 1;" ::: "memory");
        } else {
            asm volatile("cp.async.wait_group 0;" ::: "memory");
        }
        __syncthreads();

        float sacc[8][4];
#pragma unroll
        for (int nt = 0; nt < 8; nt++)
#pragma unroll
            for (int c = 0; c < 4; c++) sacc[nt][c] = 0.f;

#pragma unroll
        for (int ks = 0; ks < 4; ks++) {
            const int acol = 16 * ks + 8 * lsel;
            uint32_t ah[4], al[4];
            LDSM_X4(ah, su + (uint32_t)(E_QH + (warp * 16 + lrow) * STRD + acol) * 2);
            LDSM_X4(al, su + (uint32_t)(E_QL + (warp * 16 + lrow) * STRD + acol) * 2);
#pragma unroll
            for (int np = 0; np < 4; np++) {
                uint32_t bh[4], bl[4];
                const int krow = np * 16 + lrow;
                LDSM_X4(bh, su + (uint32_t)(E_KH(st) + krow * STRD + acol) * 2);
                LDSM_X4(bl, su + (uint32_t)(E_KL(st) + krow * STRD + acol) * 2);
                mma16816(sacc[2 * np],     ah, bh[0], bh[2]);
                mma16816(sacc[2 * np],     ah, bl[0], bl[2]);
                mma16816(sacc[2 * np],     al, bh[0], bh[2]);
                mma16816(sacc[2 * np + 1], ah, bh[1], bh[3]);
                mma16816(sacc[2 * np + 1], ah, bl[1], bl[3]);
                mma16816(sacc[2 * np + 1], al, bh[1], bh[3]);
            }
        }

        float mx0 = sacc[0][0], mx1 = sacc[0][2];
#pragma unroll
        for (int nt = 0; nt < 8; nt++) {
            mx0 = fmaxf(mx0, fmaxf(sacc[nt][0], sacc[nt][1]));
            mx1 = fmaxf(mx1, fmaxf(sacc[nt][2], sacc[nt][3]));
        }
        mx0 = qmax4(mx0); mx1 = qmax4(mx1);
        float mn0 = fmaxf(m_i[0], mx0);
        float mn1 = fmaxf(m_i[1], mx1);
        float alpha0 = __expf(m_i[0] - mn0);
        float alpha1 = __expf(m_i[1] - mn1);
        m_i[0] = mn0; m_i[1] = mn1;

        float s0 = 0.f, s1 = 0.f;
        uint32_t ph[4][4], pl[4][4];
#pragma unroll
        for (int nt = 0; nt < 8; nt++) {
            float p0 = __expf(sacc[nt][0] - mn0);
            float p1 = __expf(sacc[nt][1] - mn0);
            float p2 = __expf(sacc[nt][2] - mn1);
            float p3 = __expf(sacc[nt][3] - mn1);
            s0 += p0 + p1;  s1 += p2 + p3;
            float h0 = __bfloat162float(__float2bfloat16(p0));
            float h1 = __bfloat162float(__float2bfloat16(p1));
            float h2 = __bfloat162float(__float2bfloat16(p2));
            float h3 = __bfloat162float(__float2bfloat16(p3));
            int ks = nt >> 1, hi2 = (nt & 1) << 1;
            ph[ks][hi2 + 0] = pack_bf16x2(h0, h1);
            ph[ks][hi2 + 1] = pack_bf16x2(h2, h3);
            pl[ks][hi2 + 0] = pack_bf16x2(p0 - h0, p1 - h1);
            pl[ks][hi2 + 1] = pack_bf16x2(p2 - h2, p3 - h3);
        }
        s0 = qsum4(s0); s1 = qsum4(s1);
        l_i[0] = alpha0 * l_i[0] + s0;
        l_i[1] = alpha1 * l_i[1] + s1;

#pragma unroll
        for (int nt = 0; nt < 8; nt++) {
            oacc[nt][0] *= alpha0; oacc[nt][1] *= alpha0;
            oacc[nt][2] *= alpha1; oacc[nt][3] *= alpha1;
        }
#pragma unroll
        for (int ks = 0; ks < 4; ks++) {
            const int vrow = 16 * ks + lrow;
#pragma unroll
            for (int np = 0; np < 4; np++) {
                uint32_t bh[4], bl[4];
                const int vcol = 16 * np + 8 * lsel;
                LDSM_X4_T(bh, su + (uint32_t)(E_VH(st) + vrow * STRD + vcol) * 2);
                LDSM_X4_T(bl, su + (uint32_t)(E_VL(st) + vrow * STRD + vcol) * 2);
                mma16816(oacc[2 * np],     ph[ks], bh[0], bh[1]);
                mma16816(oacc[2 * np],     ph[ks], bl[0], bl[1]);
                mma16816(oacc[2 * np],     pl[ks], bh[0], bh[1]);
                mma16816(oacc[2 * np + 1], ph[ks], bh[2], bh[3]);
                mma16816(oacc[2 * np + 1], ph[ks], bl[2], bl[3]);
                mma16816(oacc[2 * np + 1], pl[ks], bh[2], bh[3]);
            }
        }
        __syncthreads();
    }

    float inv0 = 1.f / l_i[0];
    float inv1 = 1.f / l_i[1];
    float* op0 = out + (tokbase + q0 + r0) * HD;
    float* op1 = out + (tokbase + q0 + r0 + 8) * HD;
#pragma unroll
    for (int nt = 0; nt < 8; nt++) {
        int col = 8 * nt + 2 * tq;
        *reinterpret_cast<float2*>(op0 + col) =
            make_float2(oacc[nt][0] * inv0, oacc[nt][1] * inv0);
        *reinterpret_cast<float2*>(op1 + col) =
            make_float2(oacc[nt][2] * inv1, oacc[nt][3] * inv1);
    }
}

// ---------------------------------------------------------------------------

extern "C" void kernel_launch(void* const* d_in, const int* in_sizes, int n_in,
                              void* d_out, int out_size) {
    (void)in_sizes; (void)n_in; (void)out_size;
    const float* x = (const float*)d_in[0];   // [4,4096,1024] fp32
    const float* w = (const float*)d_in[1];   // [1024,192]   fp32
    float* out = (float*)d_out;               // [4,4096,64]  fp32

    cudaFuncSetAttribute(qkv_mma_kernel,
                         cudaFuncAttributeMaxDynamicSharedMemorySize,
                         GEMM_SMEM);
    cudaFuncSetAttribute(attn_mma_kernel,
                         cudaFuncAttributeMaxDynamicSharedMemorySize,
                         ATTN_SMEM);

    qkv_mma_kernel<<<dim3(MT / 128, 3), 256, GEMM_SMEM>>>(x, w);
    attn_mma_kernel<<<dim3(SEQ / 64, BATCH), 128, ATTN_SMEM>>>(out);
}

// round 6
// speedup vs baseline: 3.6427x; 1.0823x over previous
#include <cuda_runtime.h>
#include <cuda_bf16.h>
#include <cstdint>
#include <math.h>

#define BATCH 4
#define SEQ   4096
#define HD    64
#define EMB   1024
#define MT    (BATCH*SEQ)

// pre-split bf16 scratch (written by GEMM epilogue): [token][dim]
__device__ __align__(128) __nv_bfloat16 g_qh[MT*HD];
__device__ __align__(128) __nv_bfloat16 g_ql[MT*HD];
__device__ __align__(128) __nv_bfloat16 g_kh[MT*HD];
__device__ __align__(128) __nv_bfloat16 g_kl[MT*HD];
__device__ __align__(128) __nv_bfloat16 g_vh[MT*HD];
__device__ __align__(128) __nv_bfloat16 g_vl[MT*HD];

// ---------------------------------------------------------------------------
// PTX helpers (baseline PTX only — no sm_103a-gated features)
// ---------------------------------------------------------------------------
__device__ __forceinline__ uint32_t smem_to_u32(const void* p) {
    uint32_t a;
    asm("{ .reg .u64 t; cvta.to.shared.u64 t, %1; cvt.u32.u64 %0, t; }"
        : "=r"(a) : "l"(p));
    return a;
}

__device__ __forceinline__ void mma16816(float* d, const uint32_t* a,
                                         uint32_t b0, uint32_t b1) {
    asm volatile(
        "mma.sync.aligned.m16n8k16.row.col.f32.bf16.bf16.f32 "
        "{%0,%1,%2,%3}, {%4,%5,%6,%7}, {%8,%9}, {%0,%1,%2,%3};"
        : "+f"(d[0]), "+f"(d[1]), "+f"(d[2]), "+f"(d[3])
        : "r"(a[0]), "r"(a[1]), "r"(a[2]), "r"(a[3]),
          "r"(b0), "r"(b1));
}

#define LDSM_X4(r, addr) \
    asm volatile("ldmatrix.sync.aligned.m8n8.x4.shared.b16 {%0,%1,%2,%3}, [%4];" \
        : "=r"((r)[0]), "=r"((r)[1]), "=r"((r)[2]), "=r"((r)[3]) : "r"(addr))
#define LDSM_X4_T(r, addr) \
    asm volatile("ldmatrix.sync.aligned.m8n8.x4.trans.shared.b16 {%0,%1,%2,%3}, [%4];" \
        : "=r"((r)[0]), "=r"((r)[1]), "=r"((r)[2]), "=r"((r)[3]) : "r"(addr))

#define CP_ASYNC16(saddr, gptr) \
    asm volatile("cp.async.cg.shared.global [%0], [%1], 16;" \
        :: "r"(saddr), "l"(__cvta_generic_to_global(gptr)) : "memory")
#define CP_COMMIT() asm volatile("cp.async.commit_group;" ::: "memory")

__device__ __forceinline__ uint32_t pack_bf16x2(float lo, float hi) {
    uint32_t r;
    asm("cvt.rn.bf16x2.f32 %0, %1, %2;" : "=r"(r) : "f"(hi), "f"(lo));
    return r;
}
__device__ __forceinline__ void split2(float e0, float e1,
                                       uint32_t& hi, uint32_t& lo) {
    __nv_bfloat16 h0 = __float2bfloat16(e0);
    __nv_bfloat16 h1 = __float2bfloat16(e1);
    hi = (uint32_t)__bfloat16_as_ushort(h0) |
         ((uint32_t)__bfloat16_as_ushort(h1) << 16);
    lo = pack_bf16x2(e0 - __bfloat162float(h0), e1 - __bfloat162float(h1));
}
__device__ __forceinline__ float qmax4(float v) {
    v = fmaxf(v, __shfl_xor_sync(0xffffffffu, v, 1));
    v = fmaxf(v, __shfl_xor_sync(0xffffffffu, v, 2));
    return v;
}
__device__ __forceinline__ float qsum4(float v) {
    v += __shfl_xor_sync(0xffffffffu, v, 1);
    v += __shfl_xor_sync(0xffffffffu, v, 2);
    return v;
}

// ---------------------------------------------------------------------------
// QKV projection, tensorized bf16x3 (unchanged from round 5 — ~77us)
// ---------------------------------------------------------------------------
#define GSTR 72
#define GE_XH 0
#define GE_XL (128*GSTR)
#define GE_WH (2*128*GSTR)
#define GE_WL (GE_WH + 64*GSTR)
#define GEMM_SMEM ((2*128 + 2*64) * GSTR * 2)   // 55296 B

__global__ __launch_bounds__(256, 2) void qkv_mma_kernel(
        const float* __restrict__ x, const float* __restrict__ w) {
    extern __shared__ __nv_bfloat16 gsm[];
    const uint32_t su = smem_to_u32(gsm);
    const int tid  = threadIdx.x;
    const int lane = tid & 31;
    const int warp = tid >> 5;
    const int g    = lane >> 2;
    const int tq   = lane & 3;
    const int lrow = lane & 15;
    const int lsel = lane >> 4;
    const int m0   = blockIdx.x * 128;
    const int n0   = blockIdx.y * 64;

    float acc[8][4];
#pragma unroll
    for (int nt = 0; nt < 8; nt++)
#pragma unroll
        for (int c = 0; c < 4; c++) acc[nt][c] = 0.f;

    float4 xr[8], wr[4];
#pragma unroll
    for (int r = 0; r < 8; r++) {
        int f4 = tid + 256 * r, row = f4 >> 4, c4 = (f4 & 15) << 2;
        xr[r] = *reinterpret_cast<const float4*>(x + (size_t)(m0 + row) * EMB + c4);
    }
#pragma unroll
    for (int r = 0; r < 4; r++) {
        int f4 = tid + 256 * r, row = f4 >> 4, c4 = (f4 & 15) << 2;
        wr[r] = *reinterpret_cast<const float4*>(w + (size_t)row * 192 + n0 + c4);
    }

#pragma unroll 1
    for (int kt = 0; kt < EMB / 64; kt++) {
#pragma unroll
        for (int r = 0; r < 8; r++) {
            int f4 = tid + 256 * r, row = f4 >> 4, c = (f4 & 15) << 2;
            uint32_t h0, l0, h1, l1;
            split2(xr[r].x, xr[r].y, h0, l0);
            split2(xr[r].z, xr[r].w, h1, l1);
            *reinterpret_cast<uint2*>(gsm + GE_XH + row * GSTR + c) = make_uint2(h0, h1);
            *reinterpret_cast<uint2*>(gsm + GE_XL + row * GSTR + c) = make_uint2(l0, l1);
        }
#pragma unroll
        for (int r = 0; r < 4; r++) {
            int f4 = tid + 256 * r, row = f4 >> 4, c = (f4 & 15) << 2;
            uint32_t h0, l0, h1, l1;
            split2(wr[r].x, wr[r].y, h0, l0);
            split2(wr[r].z, wr[r].w, h1, l1);
            *reinterpret_cast<uint2*>(gsm + GE_WH + row * GSTR + c) = make_uint2(h0, h1);
            *reinterpret_cast<uint2*>(gsm + GE_WL + row * GSTR + c) = make_uint2(l0, l1);
        }
        __syncthreads();

        if (kt + 1 < EMB / 64) {
            const int kb = (kt + 1) * 64;
#pragma unroll
            for (int r = 0; r < 8; r++) {
                int f4 = tid + 256 * r, row = f4 >> 4, c4 = (f4 & 15) << 2;
                xr[r] = *reinterpret_cast<const float4*>(
                    x + (size_t)(m0 + row) * EMB + kb + c4);
            }
#pragma unroll
            for (int r = 0; r < 4; r++) {
                int f4 = tid + 256 * r, row = f4 >> 4, c4 = (f4 & 15) << 2;
                wr[r] = *reinterpret_cast<const float4*>(
                    w + (size_t)(kb + row) * 192 + n0 + c4);
            }
        }

#pragma unroll
        for (int ks = 0; ks < 4; ks++) {
            const int acol = 16 * ks + 8 * lsel;
            uint32_t ah[4], al[4];
            LDSM_X4(ah, su + (uint32_t)(GE_XH + (warp * 16 + lrow) * GSTR + acol) * 2);
            LDSM_X4(al, su + (uint32_t)(GE_XL + (warp * 16 + lrow) * GSTR + acol) * 2);
            const int wrow = 16 * ks + lrow;
#pragma unroll
            for (int np = 0; np < 4; np++) {
                uint32_t bh[4], bl[4];
                const int wcol = 16 * np + 8 * lsel;
                LDSM_X4_T(bh, su + (uint32_t)(GE_WH + wrow * GSTR + wcol) * 2);
                LDSM_X4_T(bl, su + (uint32_t)(GE_WL + wrow * GSTR + wcol) * 2);
                mma16816(acc[2 * np],     ah, bh[0], bh[1]);
                mma16816(acc[2 * np],     ah, bl[0], bl[1]);
                mma16816(acc[2 * np],     al, bh[0], bh[1]);
                mma16816(acc[2 * np + 1], ah, bh[2], bh[3]);
                mma16816(acc[2 * np + 1], ah, bl[2], bl[3]);
                mma16816(acc[2 * np + 1], al, bh[2], bh[3]);
            }
        }
        __syncthreads();
    }

    __nv_bfloat16 *oh, *ol;
    float scale = 1.f;
    if (blockIdx.y == 0)      { oh = g_qh; ol = g_ql; scale = 0.125f; }
    else if (blockIdx.y == 1) { oh = g_kh; ol = g_kl; }
    else                      { oh = g_vh; ol = g_vl; }

    const int ra = m0 + warp * 16 + g;
#pragma unroll
    for (int nt = 0; nt < 8; nt++) {
        const int c = 8 * nt + 2 * tq;
        uint32_t hi, lo;
        split2(acc[nt][0] * scale, acc[nt][1] * scale, hi, lo);
        *reinterpret_cast<uint32_t*>(oh + (size_t)ra * HD + c) = hi;
        *reinterpret_cast<uint32_t*>(ol + (size_t)ra * HD + c) = lo;
        split2(acc[nt][2] * scale, acc[nt][3] * scale, hi, lo);
        *reinterpret_cast<uint32_t*>(oh + (size_t)(ra + 8) * HD + c) = hi;
        *reinterpret_cast<uint32_t*>(ol + (size_t)(ra + 8) * HD + c) = lo;
    }
}

// ---------------------------------------------------------------------------
// Flash attention: mma.sync bf16x3, XOR-swizzled smem (no padding),
// Q fragments in registers, 3 CTAs/SM, np-pair interleaved mma issue.
// ---------------------------------------------------------------------------
#define T64 (64*64)                 // one 64x64 bf16 tile = 4096 els = 8 KB
#define E_KH(s) ((s)*4*T64)
#define E_KL(s) ((s)*4*T64 + T64)
#define E_VH(s) ((s)*4*T64 + 2*T64)
#define E_VL(s) ((s)*4*T64 + 3*T64)
#define ATTN_SMEM (8*T64*2)         // 65536 bytes

// swizzled element offset of (row, chunk) within a tile; chunk = col/8
#define SWZ(row, ch) ((row)*64 + (((ch) ^ ((row) & 7)) << 3))

__device__ __forceinline__ void tile_copy_async(
    uint32_t su, int eoff, const __nv_bfloat16* src, int tid) {
#pragma unroll
    for (int r = 0; r < 4; r++) {
        int c   = tid + 128 * r;
        int row = c >> 3;
        int ch  = c & 7;
        uint32_t sa = su + (uint32_t)(eoff + SWZ(row, ch)) * 2;
        CP_ASYNC16(sa, src + row * HD + ch * 8);
    }
}

__global__ __launch_bounds__(128, 3) void attn_mma_kernel(float* __restrict__ out) {
    extern __shared__ __nv_bfloat16 sm[];
    const uint32_t su = smem_to_u32(sm);
    const int tid  = threadIdx.x;
    const int lane = tid & 31;
    const int warp = tid >> 5;
    const int g    = lane >> 2;
    const int tq   = lane & 3;
    const int lrow = lane & 15;
    const int lsel = lane >> 4;
    const int b    = blockIdx.y;
    const int q0   = blockIdx.x * 64;
    const int r0   = warp * 16 + g;

    const size_t tokbase = (size_t)b * SEQ;

    // ---- stage Q through smem once, keep fragments in registers ----
    {
        const __nv_bfloat16* qh = g_qh + (tokbase + q0) * HD;
        const __nv_bfloat16* ql = g_ql + (tokbase + q0) * HD;
#pragma unroll
        for (int r = 0; r < 8; r++) {
            int c   = tid + 128 * (r & 3);
            int row = c >> 3;
            int ch  = c & 7;
            const __nv_bfloat16* src = (r < 4 ? qh : ql) + row * HD + ch * 8;
            uint4 v = *reinterpret_cast<const uint4*>(src);
            *reinterpret_cast<uint4*>(sm + (r < 4 ? 0 : T64) + SWZ(row, ch)) = v;
        }
    }
    __syncthreads();
    uint32_t aH[4][4], aL[4][4];
#pragma unroll
    for (int ks = 0; ks < 4; ks++) {
        const int R  = warp * 16 + lrow;
        const int cb = 2 * ks + lsel;
        LDSM_X4(aH[ks], su + (uint32_t)(SWZ(R, cb)) * 2);
        LDSM_X4(aL[ks], su + (uint32_t)(T64 + SWZ(R, cb)) * 2);
    }
    __syncthreads();

    // ---- prologue: stage 0 of K/V pipeline ----
    tile_copy_async(su, E_KH(0), g_kh + tokbase * HD, tid);
    tile_copy_async(su, E_KL(0), g_kl + tokbase * HD, tid);
    tile_copy_async(su, E_VH(0), g_vh + tokbase * HD, tid);
    tile_copy_async(su, E_VL(0), g_vl + tokbase * HD, tid);
    CP_COMMIT();

    float m_i[2] = {-1e30f, -1e30f};
    float l_i[2] = {0.f, 0.f};
    float oacc[8][4];
#pragma unroll
    for (int nt = 0; nt < 8; nt++)
#pragma unroll
        for (int c = 0; c < 4; c++) oacc[nt][c] = 0.f;

#pragma unroll 1
    for (int t = 0; t < SEQ / 64; t++) {
        const int st = t & 1;
        if (t + 1 < SEQ / 64) {
            const size_t nb = (tokbase + (t + 1) * 64) * HD;
            const int ns = (t + 1) & 1;
            tile_copy_async(su, E_KH(ns), g_kh + nb, tid);
            tile_copy_async(su, E_KL(ns), g_kl + nb, tid);
            tile_copy_async(su, E_VH(ns), g_vh + nb, tid);
            tile_copy_async(su, E_VL(ns), g_vl + nb, tid);
            CP_COMMIT();
            asm volatile("cp.async.wait_group 1;" ::: "memory");
        } else {
            asm volatile("cp.async.wait_group 0;" ::: "memory");
        }
        __syncthreads();

        // ---- S = Q K^T : np-pair interleaved (RAW distance 4) ----
        float sacc[8][4];
#pragma unroll
        for (int nt = 0; nt < 8; nt++)
#pragma unroll
            for (int c = 0; c < 4; c++) sacc[nt][c] = 0.f;

#pragma unroll
        for (int ks = 0; ks < 4; ks++) {
            const int cb = 2 * ks + lsel;
#pragma unroll
            for (int npp = 0; npp < 2; npp++) {
                const int k0 = (2 * npp) * 16 + lrow;
                const int k1 = (2 * npp + 1) * 16 + lrow;
                uint32_t bh0[4], bh1[4], bl0[4], bl1[4];
                LDSM_X4(bh0, su + (uint32_t)(E_KH(st) + SWZ(k0, cb)) * 2);
                LDSM_X4(bh1, su + (uint32_t)(E_KH(st) + SWZ(k1, cb)) * 2);
                LDSM_X4(bl0, su + (uint32_t)(E_KL(st) + SWZ(k0, cb)) * 2);
                LDSM_X4(bl1, su + (uint32_t)(E_KL(st) + SWZ(k1, cb)) * 2);
                float* s0 = sacc[4 * npp + 0];
                float* s1 = sacc[4 * npp + 1];
                float* s2 = sacc[4 * npp + 2];
                float* s3 = sacc[4 * npp + 3];
                mma16816(s0, aH[ks], bh0[0], bh0[2]);
                mma16816(s1, aH[ks], bh0[1], bh0[3]);
                mma16816(s2, aH[ks], bh1[0], bh1[2]);
                mma16816(s3, aH[ks], bh1[1], bh1[3]);
                mma16816(s0, aH[ks], bl0[0], bl0[2]);
                mma16816(s1, aH[ks], bl0[1], bl0[3]);
                mma16816(s2, aH[ks], bl1[0], bl1[2]);
                mma16816(s3, aH[ks], bl1[1], bl1[3]);
                mma16816(s0, aL[ks], bh0[0], bh0[2]);
                mma16816(s1, aL[ks], bh0[1], bh0[3]);
                mma16816(s2, aL[ks], bh1[0], bh1[2]);
                mma16816(s3, aL[ks], bh1[1], bh1[3]);
            }
        }

        // ---- online softmax on register fragments ----
        float mx0 = sacc[0][0], mx1 = sacc[0][2];
#pragma unroll
        for (int nt = 0; nt < 8; nt++) {
            mx0 = fmaxf(mx0, fmaxf(sacc[nt][0], sacc[nt][1]));
            mx1 = fmaxf(mx1, fmaxf(sacc[nt][2], sacc[nt][3]));
        }
        mx0 = qmax4(mx0); mx1 = qmax4(mx1);
        float mn0 = fmaxf(m_i[0], mx0);
        float mn1 = fmaxf(m_i[1], mx1);
        float alpha0 = __expf(m_i[0] - mn0);
        float alpha1 = __expf(m_i[1] - mn1);
        m_i[0] = mn0; m_i[1] = mn1;

        float s0 = 0.f, s1 = 0.f;
        uint32_t ph[4][4], pl[4][4];
#pragma unroll
        for (int nt = 0; nt < 8; nt++) {
            float p0 = __expf(sacc[nt][0] - mn0);
            float p1 = __expf(sacc[nt][1] - mn0);
            float p2 = __expf(sacc[nt][2] - mn1);
            float p3 = __expf(sacc[nt][3] - mn1);
            s0 += p0 + p1;  s1 += p2 + p3;
            float h0 = __bfloat162float(__float2bfloat16(p0));
            float h1 = __bfloat162float(__float2bfloat16(p1));
            float h2 = __bfloat162float(__float2bfloat16(p2));
            float h3 = __bfloat162float(__float2bfloat16(p3));
            int ks = nt >> 1, hi2 = (nt & 1) << 1;
            ph[ks][hi2 + 0] = pack_bf16x2(h0, h1);
            ph[ks][hi2 + 1] = pack_bf16x2(h2, h3);
            pl[ks][hi2 + 0] = pack_bf16x2(p0 - h0, p1 - h1);
            pl[ks][hi2 + 1] = pack_bf16x2(p2 - h2, p3 - h3);
        }
        s0 = qsum4(s0); s1 = qsum4(s1);
        l_i[0] = alpha0 * l_i[0] + s0;
        l_i[1] = alpha1 * l_i[1] + s1;

        // ---- rescale O, then O += P V (np-pair interleaved) ----
#pragma unroll
        for (int nt = 0; nt < 8; nt++) {
            oacc[nt][0] *= alpha0; oacc[nt][1] *= alpha0;
            oacc[nt][2] *= alpha1; oacc[nt][3] *= alpha1;
        }
#pragma unroll
        for (int ks = 0; ks < 4; ks++) {
            const int vr = 16 * ks + lrow;
#pragma unroll
            for (int npp = 0; npp < 2; npp++) {
                const int cb0 = 2 * (2 * npp) + lsel;
                const int cb1 = 2 * (2 * npp + 1) + lsel;
                uint32_t vh0[4], vh1[4], vl0[4], vl1[4];
                LDSM_X4_T(vh0, su + (uint32_t)(E_VH(st) + SWZ(vr, cb0)) * 2);
                LDSM_X4_T(vh1, su + (uint32_t)(E_VH(st) + SWZ(vr, cb1)) * 2);
                LDSM_X4_T(vl0, su + (uint32_t)(E_VL(st) + SWZ(vr, cb0)) * 2);
                LDSM_X4_T(vl1, su + (uint32_t)(E_VL(st) + SWZ(vr, cb1)) * 2);
                float* o0 = oacc[4 * npp + 0];
                float* o1 = oacc[4 * npp + 1];
                float* o2 = oacc[4 * npp + 2];
                float* o3 = oacc[4 * npp + 3];
                mma16816(o0, ph[ks], vh0[0], vh0[1]);
                mma16816(o1, ph[ks], vh0[2], vh0[3]);
                mma16816(o2, ph[ks], vh1[0], vh1[1]);
                mma16816(o3, ph[ks], vh1[2], vh1[3]);
                mma16816(o0, ph[ks], vl0[0], vl0[1]);
                mma16816(o1, ph[ks], vl0[2], vl0[3]);
                mma16816(o2, ph[ks], vl1[0], vl1[1]);
                mma16816(o3, ph[ks], vl1[2], vl1[3]);
                mma16816(o0, pl[ks], vh0[0], vh0[1]);
                mma16816(o1, pl[ks], vh0[2], vh0[3]);
                mma16816(o2, pl[ks], vh1[0], vh1[1]);
                mma16816(o3, pl[ks], vh1[2], vh1[3]);
            }
        }
        __syncthreads();
    }

    // ---- epilogue: normalize and store ----
    float inv0 = 1.f / l_i[0];
    float inv1 = 1.f / l_i[1];
    float* op0 = out + (tokbase + q0 + r0) * HD;
    float* op1 = out + (tokbase + q0 + r0 + 8) * HD;
#pragma unroll
    for (int nt = 0; nt < 8; nt++) {
        int col = 8 * nt + 2 * tq;
        *reinterpret_cast<float2*>(op0 + col) =
            make_float2(oacc[nt][0] * inv0, oacc[nt][1] * inv0);
        *reinterpret_cast<float2*>(op1 + col) =
            make_float2(oacc[nt][2] * inv1, oacc[nt][3] * inv1);
    }
}

// ---------------------------------------------------------------------------

extern "C" void kernel_launch(void* const* d_in, const int* in_sizes, int n_in,
                              void* d_out, int out_size) {
    (void)in_sizes; (void)n_in; (void)out_size;
    const float* x = (const float*)d_in[0];   // [4,4096,1024] fp32
    const float* w = (const float*)d_in[1];   // [1024,192]   fp32
    float* out = (float*)d_out;               // [4,4096,64]  fp32

    cudaFuncSetAttribute(qkv_mma_kernel,
                         cudaFuncAttributeMaxDynamicSharedMemorySize,
                         GEMM_SMEM);
    cudaFuncSetAttribute(attn_mma_kernel,
                         cudaFuncAttributeMaxDynamicSharedMemorySize,
                         ATTN_SMEM);

    qkv_mma_kernel<<<dim3(MT / 128, 3), 256, GEMM_SMEM>>>(x, w);
    attn_mma_kernel<<<dim3(SEQ / 64, BATCH), 128, ATTN_SMEM>>>(out);
}

// round 7
// speedup vs baseline: 3.6521x; 1.0026x over previous
#include <cuda_runtime.h>
#include <cuda_bf16.h>
#include <cstdint>
#include <math.h>

#define BATCH 4
#define SEQ   4096
#define HD    64
#define EMB   1024
#define MT    (BATCH*SEQ)
#define NSPL  2
#define KT_PER (SEQ/64/NSPL)   // 32 k-tiles per split

// pre-split bf16 scratch (written by GEMM epilogue): [token][dim]
__device__ __align__(128) __nv_bfloat16 g_qh[MT*HD];
__device__ __align__(128) __nv_bfloat16 g_ql[MT*HD];
__device__ __align__(128) __nv_bfloat16 g_kh[MT*HD];
__device__ __align__(128) __nv_bfloat16 g_kl[MT*HD];
__device__ __align__(128) __nv_bfloat16 g_vh[MT*HD];
__device__ __align__(128) __nv_bfloat16 g_vl[MT*HD];

// split-KV partials
__device__ __align__(128) float g_po[NSPL][MT*HD];   // unnormalized O
__device__ float g_pm[NSPL][MT];                     // row max
__device__ float g_pl[NSPL][MT];                     // row sum

// ---------------------------------------------------------------------------
// PTX helpers (baseline PTX only — no sm_103a-gated features)
// ---------------------------------------------------------------------------
__device__ __forceinline__ uint32_t smem_to_u32(const void* p) {
    uint32_t a;
    asm("{ .reg .u64 t; cvta.to.shared.u64 t, %1; cvt.u32.u64 %0, t; }"
        : "=r"(a) : "l"(p));
    return a;
}

__device__ __forceinline__ void mma16816(float* d, const uint32_t* a,
                                         uint32_t b0, uint32_t b1) {
    asm volatile(
        "mma.sync.aligned.m16n8k16.row.col.f32.bf16.bf16.f32 "
        "{%0,%1,%2,%3}, {%4,%5,%6,%7}, {%8,%9}, {%0,%1,%2,%3};"
        : "+f"(d[0]), "+f"(d[1]), "+f"(d[2]), "+f"(d[3])
        : "r"(a[0]), "r"(a[1]), "r"(a[2]), "r"(a[3]),
          "r"(b0), "r"(b1));
}

#define LDSM_X4(r, addr) \
    asm volatile("ldmatrix.sync.aligned.m8n8.x4.shared.b16 {%0,%1,%2,%3}, [%4];" \
        : "=r"((r)[0]), "=r"((r)[1]), "=r"((r)[2]), "=r"((r)[3]) : "r"(addr))
#define LDSM_X4_T(r, addr) \
    asm volatile("ldmatrix.sync.aligned.m8n8.x4.trans.shared.b16 {%0,%1,%2,%3}, [%4];" \
        : "=r"((r)[0]), "=r"((r)[1]), "=r"((r)[2]), "=r"((r)[3]) : "r"(addr))

#define CP_ASYNC16(saddr, gptr) \
    asm volatile("cp.async.cg.shared.global [%0], [%1], 16;" \
        :: "r"(saddr), "l"(__cvta_generic_to_global(gptr)) : "memory")
#define CP_COMMIT() asm volatile("cp.async.commit_group;" ::: "memory")

__device__ __forceinline__ uint32_t pack_bf16x2(float lo, float hi) {
    uint32_t r;
    asm("cvt.rn.bf16x2.f32 %0, %1, %2;" : "=r"(r) : "f"(hi), "f"(lo));
    return r;
}
__device__ __forceinline__ void split2(float e0, float e1,
                                       uint32_t& hi, uint32_t& lo) {
    __nv_bfloat16 h0 = __float2bfloat16(e0);
    __nv_bfloat16 h1 = __float2bfloat16(e1);
    hi = (uint32_t)__bfloat16_as_ushort(h0) |
         ((uint32_t)__bfloat16_as_ushort(h1) << 16);
    lo = pack_bf16x2(e0 - __bfloat162float(h0), e1 - __bfloat162float(h1));
}
__device__ __forceinline__ float qmax4(float v) {
    v = fmaxf(v, __shfl_xor_sync(0xffffffffu, v, 1));
    v = fmaxf(v, __shfl_xor_sync(0xffffffffu, v, 2));
    return v;
}
__device__ __forceinline__ float qsum4(float v) {
    v += __shfl_xor_sync(0xffffffffu, v, 1);
    v += __shfl_xor_sync(0xffffffffu, v, 2);
    return v;
}

// ---------------------------------------------------------------------------
// QKV projection, tensorized bf16x3 (unchanged — ~73us)
// ---------------------------------------------------------------------------
#define GSTR 72
#define GE_XH 0
#define GE_XL (128*GSTR)
#define GE_WH (2*128*GSTR)
#define GE_WL (GE_WH + 64*GSTR)
#define GEMM_SMEM ((2*128 + 2*64) * GSTR * 2)   // 55296 B

__global__ __launch_bounds__(256, 2) void qkv_mma_kernel(
        const float* __restrict__ x, const float* __restrict__ w) {
    extern __shared__ __nv_bfloat16 gsm[];
    const uint32_t su = smem_to_u32(gsm);
    const int tid  = threadIdx.x;
    const int lane = tid & 31;
    const int warp = tid >> 5;
    const int g    = lane >> 2;
    const int tq   = lane & 3;
    const int lrow = lane & 15;
    const int lsel = lane >> 4;
    const int m0   = blockIdx.x * 128;
    const int n0   = blockIdx.y * 64;

    float acc[8][4];
#pragma unroll
    for (int nt = 0; nt < 8; nt++)
#pragma unroll
        for (int c = 0; c < 4; c++) acc[nt][c] = 0.f;

    float4 xr[8], wr[4];
#pragma unroll
    for (int r = 0; r < 8; r++) {
        int f4 = tid + 256 * r, row = f4 >> 4, c4 = (f4 & 15) << 2;
        xr[r] = *reinterpret_cast<const float4*>(x + (size_t)(m0 + row) * EMB + c4);
    }
#pragma unroll
    for (int r = 0; r < 4; r++) {
        int f4 = tid + 256 * r, row = f4 >> 4, c4 = (f4 & 15) << 2;
        wr[r] = *reinterpret_cast<const float4*>(w + (size_t)row * 192 + n0 + c4);
    }

#pragma unroll 1
    for (int kt = 0; kt < EMB / 64; kt++) {
#pragma unroll
        for (int r = 0; r < 8; r++) {
            int f4 = tid + 256 * r, row = f4 >> 4, c = (f4 & 15) << 2;
            uint32_t h0, l0, h1, l1;
            split2(xr[r].x, xr[r].y, h0, l0);
            split2(xr[r].z, xr[r].w, h1, l1);
            *reinterpret_cast<uint2*>(gsm + GE_XH + row * GSTR + c) = make_uint2(h0, h1);
            *reinterpret_cast<uint2*>(gsm + GE_XL + row * GSTR + c) = make_uint2(l0, l1);
        }
#pragma unroll
        for (int r = 0; r < 4; r++) {
            int f4 = tid + 256 * r, row = f4 >> 4, c = (f4 & 15) << 2;
            uint32_t h0, l0, h1, l1;
            split2(wr[r].x, wr[r].y, h0, l0);
            split2(wr[r].z, wr[r].w, h1, l1);
            *reinterpret_cast<uint2*>(gsm + GE_WH + row * GSTR + c) = make_uint2(h0, h1);
            *reinterpret_cast<uint2*>(gsm + GE_WL + row * GSTR + c) = make_uint2(l0, l1);
        }
        __syncthreads();

        if (kt + 1 < EMB / 64) {
            const int kb = (kt + 1) * 64;
#pragma unroll
            for (int r = 0; r < 8; r++) {
                int f4 = tid + 256 * r, row = f4 >> 4, c4 = (f4 & 15) << 2;
                xr[r] = *reinterpret_cast<const float4*>(
                    x + (size_t)(m0 + row) * EMB + kb + c4);
            }
#pragma unroll
            for (int r = 0; r < 4; r++) {
                int f4 = tid + 256 * r, row = f4 >> 4, c4 = (f4 & 15) << 2;
                wr[r] = *reinterpret_cast<const float4*>(
                    w + (size_t)(kb + row) * 192 + n0 + c4);
            }
        }

#pragma unroll
        for (int ks = 0; ks < 4; ks++) {
            const int acol = 16 * ks + 8 * lsel;
            uint32_t ah[4], al[4];
            LDSM_X4(ah, su + (uint32_t)(GE_XH + (warp * 16 + lrow) * GSTR + acol) * 2);
            LDSM_X4(al, su + (uint32_t)(GE_XL + (warp * 16 + lrow) * GSTR + acol) * 2);
            const int wrow = 16 * ks + lrow;
#pragma unroll
            for (int np = 0; np < 4; np++) {
                uint32_t bh[4], bl[4];
                const int wcol = 16 * np + 8 * lsel;
                LDSM_X4_T(bh, su + (uint32_t)(GE_WH + wrow * GSTR + wcol) * 2);
                LDSM_X4_T(bl, su + (uint32_t)(GE_WL + wrow * GSTR + wcol) * 2);
                mma16816(acc[2 * np],     ah, bh[0], bh[1]);
                mma16816(acc[2 * np],     ah, bl[0], bl[1]);
                mma16816(acc[2 * np],     al, bh[0], bh[1]);
                mma16816(acc[2 * np + 1], ah, bh[2], bh[3]);
                mma16816(acc[2 * np + 1], ah, bl[2], bl[3]);
                mma16816(acc[2 * np + 1], al, bh[2], bh[3]);
            }
        }
        __syncthreads();
    }

    __nv_bfloat16 *oh, *ol;
    float scale = 1.f;
    if (blockIdx.y == 0)      { oh = g_qh; ol = g_ql; scale = 0.125f; }
    else if (blockIdx.y == 1) { oh = g_kh; ol = g_kl; }
    else                      { oh = g_vh; ol = g_vl; }

    const int ra = m0 + warp * 16 + g;
#pragma unroll
    for (int nt = 0; nt < 8; nt++) {
        const int c = 8 * nt + 2 * tq;
        uint32_t hi, lo;
        split2(acc[nt][0] * scale, acc[nt][1] * scale, hi, lo);
        *reinterpret_cast<uint32_t*>(oh + (size_t)ra * HD + c) = hi;
        *reinterpret_cast<uint32_t*>(ol + (size_t)ra * HD + c) = lo;
        split2(acc[nt][2] * scale, acc[nt][3] * scale, hi, lo);
        *reinterpret_cast<uint32_t*>(oh + (size_t)(ra + 8) * HD + c) = hi;
        *reinterpret_cast<uint32_t*>(ol + (size_t)(ra + 8) * HD + c) = lo;
    }
}

// ---------------------------------------------------------------------------
// Flash attention, split-KV: grid (64, 4, 2); each CTA does 32 k-tiles and
// writes unnormalized partial O + (m,l) to scratch.
// ---------------------------------------------------------------------------
#define T64 (64*64)
#define E_KH(s) ((s)*4*T64)
#define E_KL(s) ((s)*4*T64 + T64)
#define E_VH(s) ((s)*4*T64 + 2*T64)
#define E_VL(s) ((s)*4*T64 + 3*T64)
#define ATTN_SMEM (8*T64*2)         // 65536 bytes

#define SWZ(row, ch) ((row)*64 + (((ch) ^ ((row) & 7)) << 3))

__device__ __forceinline__ void tile_copy_async(
    uint32_t su, int eoff, const __nv_bfloat16* src, int tid) {
#pragma unroll
    for (int r = 0; r < 4; r++) {
        int c   = tid + 128 * r;
        int row = c >> 3;
        int ch  = c & 7;
        uint32_t sa = su + (uint32_t)(eoff + SWZ(row, ch)) * 2;
        CP_ASYNC16(sa, src + row * HD + ch * 8);
    }
}

__global__ __launch_bounds__(128, 3) void attn_mma_kernel() {
    extern __shared__ __nv_bfloat16 sm[];
    const uint32_t su = smem_to_u32(sm);
    const int tid  = threadIdx.x;
    const int lane = tid & 31;
    const int warp = tid >> 5;
    const int g    = lane >> 2;
    const int tq   = lane & 3;
    const int lrow = lane & 15;
    const int lsel = lane >> 4;
    const int b    = blockIdx.y;
    const int q0   = blockIdx.x * 64;
    const int spl  = blockIdx.z;
    const int r0   = warp * 16 + g;
    const int t0   = spl * KT_PER;

    const size_t tokbase = (size_t)b * SEQ;

    // ---- stage Q through smem once, keep fragments in registers ----
    {
        const __nv_bfloat16* qh = g_qh + (tokbase + q0) * HD;
        const __nv_bfloat16* ql = g_ql + (tokbase + q0) * HD;
#pragma unroll
        for (int r = 0; r < 8; r++) {
            int c   = tid + 128 * (r & 3);
            int row = c >> 3;
            int ch  = c & 7;
            const __nv_bfloat16* src = (r < 4 ? qh : ql) + row * HD + ch * 8;
            uint4 v = *reinterpret_cast<const uint4*>(src);
            *reinterpret_cast<uint4*>(sm + (r < 4 ? 0 : T64) + SWZ(row, ch)) = v;
        }
    }
    __syncthreads();
    uint32_t aH[4][4], aL[4][4];
#pragma unroll
    for (int ks = 0; ks < 4; ks++) {
        const int R  = warp * 16 + lrow;
        const int cb = 2 * ks + lsel;
        LDSM_X4(aH[ks], su + (uint32_t)(SWZ(R, cb)) * 2);
        LDSM_X4(aL[ks], su + (uint32_t)(T64 + SWZ(R, cb)) * 2);
    }
    __syncthreads();

    // ---- prologue: first tile of this split ----
    tile_copy_async(su, E_KH(0), g_kh + (tokbase + t0 * 64) * HD, tid);
    tile_copy_async(su, E_KL(0), g_kl + (tokbase + t0 * 64) * HD, tid);
    tile_copy_async(su, E_VH(0), g_vh + (tokbase + t0 * 64) * HD, tid);
    tile_copy_async(su, E_VL(0), g_vl + (tokbase + t0 * 64) * HD, tid);
    CP_COMMIT();

    float m_i[2] = {-1e30f, -1e30f};
    float l_i[2] = {0.f, 0.f};
    float oacc[8][4];
#pragma unroll
    for (int nt = 0; nt < 8; nt++)
#pragma unroll
        for (int c = 0; c < 4; c++) oacc[nt][c] = 0.f;

#pragma unroll 1
    for (int tt = 0; tt < KT_PER; tt++) {
        const int st = tt & 1;
        if (tt + 1 < KT_PER) {
            const size_t nb = (tokbase + (t0 + tt + 1) * 64) * HD;
            const int ns = (tt + 1) & 1;
            tile_copy_async(su, E_KH(ns), g_kh + nb, tid);
            tile_copy_async(su, E_KL(ns), g_kl + nb, tid);
            tile_copy_async(su, E_VH(ns), g_vh + nb, tid);
            tile_copy_async(su, E_VL(ns), g_vl + nb, tid);
            CP_COMMIT();
            asm volatile("cp.async.wait_group 1;" ::: "memory");
        } else {
            asm volatile("cp.async.wait_group 0;" ::: "memory");
        }
        __syncthreads();

        // ---- S = Q K^T : np-pair interleaved ----
        float sacc[8][4];
#pragma unroll
        for (int nt = 0; nt < 8; nt++)
#pragma unroll
            for (int c = 0; c < 4; c++) sacc[nt][c] = 0.f;

#pragma unroll
        for (int ks = 0; ks < 4; ks++) {
            const int cb = 2 * ks + lsel;
#pragma unroll
            for (int npp = 0; npp < 2; npp++) {
                const int k0 = (2 * npp) * 16 + lrow;
                const int k1 = (2 * npp + 1) * 16 + lrow;
                uint32_t bh0[4], bh1[4], bl0[4], bl1[4];
                LDSM_X4(bh0, su + (uint32_t)(E_KH(st) + SWZ(k0, cb)) * 2);
                LDSM_X4(bh1, su + (uint32_t)(E_KH(st) + SWZ(k1, cb)) * 2);
                LDSM_X4(bl0, su + (uint32_t)(E_KL(st) + SWZ(k0, cb)) * 2);
                LDSM_X4(bl1, su + (uint32_t)(E_KL(st) + SWZ(k1, cb)) * 2);
                float* s0 = sacc[4 * npp + 0];
                float* s1 = sacc[4 * npp + 1];
                float* s2 = sacc[4 * npp + 2];
                float* s3 = sacc[4 * npp + 3];
                mma16816(s0, aH[ks], bh0[0], bh0[2]);
                mma16816(s1, aH[ks], bh0[1], bh0[3]);
                mma16816(s2, aH[ks], bh1[0], bh1[2]);
                mma16816(s3, aH[ks], bh1[1], bh1[3]);
                mma16816(s0, aH[ks], bl0[0], bl0[2]);
                mma16816(s1, aH[ks], bl0[1], bl0[3]);
                mma16816(s2, aH[ks], bl1[0], bl1[2]);
                mma16816(s3, aH[ks], bl1[1], bl1[3]);
                mma16816(s0, aL[ks], bh0[0], bh0[2]);
                mma16816(s1, aL[ks], bh0[1], bh0[3]);
                mma16816(s2, aL[ks], bh1[0], bh1[2]);
                mma16816(s3, aL[ks], bh1[1], bh1[3]);
            }
        }

        // ---- online softmax ----
        float mx0 = sacc[0][0], mx1 = sacc[0][2];
#pragma unroll
        for (int nt = 0; nt < 8; nt++) {
            mx0 = fmaxf(mx0, fmaxf(sacc[nt][0], sacc[nt][1]));
            mx1 = fmaxf(mx1, fmaxf(sacc[nt][2], sacc[nt][3]));
        }
        mx0 = qmax4(mx0); mx1 = qmax4(mx1);
        float mn0 = fmaxf(m_i[0], mx0);
        float mn1 = fmaxf(m_i[1], mx1);
        float alpha0 = __expf(m_i[0] - mn0);
        float alpha1 = __expf(m_i[1] - mn1);
        m_i[0] = mn0; m_i[1] = mn1;

        float s0 = 0.f, s1 = 0.f;
        uint32_t ph[4][4], pl[4][4];
#pragma unroll
        for (int nt = 0; nt < 8; nt++) {
            float p0 = __expf(sacc[nt][0] - mn0);
            float p1 = __expf(sacc[nt][1] - mn0);
            float p2 = __expf(sacc[nt][2] - mn1);
            float p3 = __expf(sacc[nt][3] - mn1);
            s0 += p0 + p1;  s1 += p2 + p3;
            float h0 = __bfloat162float(__float2bfloat16(p0));
            float h1 = __bfloat162float(__float2bfloat16(p1));
            float h2 = __bfloat162float(__float2bfloat16(p2));
            float h3 = __bfloat162float(__float2bfloat16(p3));
            int ks = nt >> 1, hi2 = (nt & 1) << 1;
            ph[ks][hi2 + 0] = pack_bf16x2(h0, h1);
            ph[ks][hi2 + 1] = pack_bf16x2(h2, h3);
            pl[ks][hi2 + 0] = pack_bf16x2(p0 - h0, p1 - h1);
            pl[ks][hi2 + 1] = pack_bf16x2(p2 - h2, p3 - h3);
        }
        s0 = qsum4(s0); s1 = qsum4(s1);
        l_i[0] = alpha0 * l_i[0] + s0;
        l_i[1] = alpha1 * l_i[1] + s1;

        // ---- rescale O, then O += P V ----
#pragma unroll
        for (int nt = 0; nt < 8; nt++) {
            oacc[nt][0] *= alpha0; oacc[nt][1] *= alpha0;
            oacc[nt][2] *= alpha1; oacc[nt][3] *= alpha1;
        }
#pragma unroll
        for (int ks = 0; ks < 4; ks++) {
            const int vr = 16 * ks + lrow;
#pragma unroll
            for (int npp = 0; npp < 2; npp++) {
                const int cb0 = 2 * (2 * npp) + lsel;
                const int cb1 = 2 * (2 * npp + 1) + lsel;
                uint32_t vh0[4], vh1[4], vl0[4], vl1[4];
                LDSM_X4_T(vh0, su + (uint32_t)(E_VH(st) + SWZ(vr, cb0)) * 2);
                LDSM_X4_T(vh1, su + (uint32_t)(E_VH(st) + SWZ(vr, cb1)) * 2);
                LDSM_X4_T(vl0, su + (uint32_t)(E_VL(st) + SWZ(vr, cb0)) * 2);
                LDSM_X4_T(vl1, su + (uint32_t)(E_VL(st) + SWZ(vr, cb1)) * 2);
                float* o0 = oacc[4 * npp + 0];
                float* o1 = oacc[4 * npp + 1];
                float* o2 = oacc[4 * npp + 2];
                float* o3 = oacc[4 * npp + 3];
                mma16816(o0, ph[ks], vh0[0], vh0[1]);
                mma16816(o1, ph[ks], vh0[2], vh0[3]);
                mma16816(o2, ph[ks], vh1[0], vh1[1]);
                mma16816(o3, ph[ks], vh1[2], vh1[3]);
                mma16816(o0, ph[ks], vl0[0], vl0[1]);
                mma16816(o1, ph[ks], vl0[2], vl0[3]);
                mma16816(o2, ph[ks], vl1[0], vl1[1]);
                mma16816(o3, ph[ks], vl1[2], vl1[3]);
                mma16816(o0, pl[ks], vh0[0], vh0[1]);
                mma16816(o1, pl[ks], vh0[2], vh0[3]);
                mma16816(o2, pl[ks], vh1[0], vh1[1]);
                mma16816(o3, pl[ks], vh1[2], vh1[3]);
            }
        }
        __syncthreads();
    }

    // ---- epilogue: write unnormalized partial O + (m,l) ----
    const size_t row0 = tokbase + q0 + r0;
    float* po = g_po[spl];
#pragma unroll
    for (int nt = 0; nt < 8; nt++) {
        int col = 8 * nt + 2 * tq;
        *reinterpret_cast<float2*>(po + row0 * HD + col) =
            make_float2(oacc[nt][0], oacc[nt][1]);
        *reinterpret_cast<float2*>(po + (row0 + 8) * HD + col) =
            make_float2(oacc[nt][2], oacc[nt][3]);
    }
    if (tq == 0) {
        g_pm[spl][row0] = m_i[0];       g_pl[spl][row0] = l_i[0];
        g_pm[spl][row0 + 8] = m_i[1];   g_pl[spl][row0 + 8] = l_i[1];
    }
}

// ---------------------------------------------------------------------------
// Combine the NSPL partials: out = sum_s a_s O_s / sum_s a_s l_s
// ---------------------------------------------------------------------------
__global__ __launch_bounds__(256) void combine_kernel(float* __restrict__ out) {
    int idx = blockIdx.x * 256 + threadIdx.x;   // one float4 per thread
    int row = idx >> 4;
    int c4  = (idx & 15) << 2;
    float m0 = g_pm[0][row], m1 = g_pm[1][row];
    float M  = fmaxf(m0, m1);
    float a0 = __expf(m0 - M), a1 = __expf(m1 - M);
    float inv = 1.f / (a0 * g_pl[0][row] + a1 * g_pl[1][row]);
    float4 o0 = *reinterpret_cast<const float4*>(g_po[0] + (size_t)row * HD + c4);
    float4 o1 = *reinterpret_cast<const float4*>(g_po[1] + (size_t)row * HD + c4);
    float4 r;
    r.x = (a0 * o0.x + a1 * o1.x) * inv;
    r.y = (a0 * o0.y + a1 * o1.y) * inv;
    r.z = (a0 * o0.z + a1 * o1.z) * inv;
    r.w = (a0 * o0.w + a1 * o1.w) * inv;
    *reinterpret_cast<float4*>(out + (size_t)row * HD + c4) = r;
}

// ---------------------------------------------------------------------------

extern "C" void kernel_launch(void* const* d_in, const int* in_sizes, int n_in,
                              void* d_out, int out_size) {
    (void)in_sizes; (void)n_in; (void)out_size;
    const float* x = (const float*)d_in[0];   // [4,4096,1024] fp32
    const float* w = (const float*)d_in[1];   // [1024,192]   fp32
    float* out = (float*)d_out;               // [4,4096,64]  fp32

    cudaFuncSetAttribute(qkv_mma_kernel,
                         cudaFuncAttributeMaxDynamicSharedMemorySize,
                         GEMM_SMEM);
    cudaFuncSetAttribute(attn_mma_kernel,
                         cudaFuncAttributeMaxDynamicSharedMemorySize,
                         ATTN_SMEM);

    qkv_mma_kernel<<<dim3(MT / 128, 3), 256, GEMM_SMEM>>>(x, w);
    attn_mma_kernel<<<dim3(SEQ / 64, BATCH, NSPL), 128, ATTN_SMEM>>>();
    combine_kernel<<<MT * HD / 4 / 256, 256>>>(out);
}

// round 8
// speedup vs baseline: 4.6862x; 1.2832x over previous
#include <cuda_runtime.h>
#include <cuda_bf16.h>
#include <cuda_fp16.h>
#include <cstdint>
#include <math.h>

#define BATCH 4
#define SEQ   4096
#define HD    64
#define EMB   1024
#define MT    (BATCH*SEQ)
#define NSPL  2
#define KT_PER (SEQ/64/NSPL)   // 32 k-tiles per split

// scratch written by GEMM epilogue
__device__ __align__(128) __nv_bfloat16 g_qh[MT*HD];
__device__ __align__(128) __nv_bfloat16 g_ql[MT*HD];
__device__ __align__(128) __nv_bfloat16 g_kh[MT*HD];
__device__ __align__(128) __nv_bfloat16 g_kl[MT*HD];
__device__ __align__(128) __half        g_vf[MT*HD];   // V as plain fp16

// split-KV partials
__device__ __align__(128) float g_po[NSPL][MT*HD];
__device__ float g_pm[NSPL][MT];
__device__ float g_pl[NSPL][MT];

// ---------------------------------------------------------------------------
// PTX helpers (baseline PTX only)
// ---------------------------------------------------------------------------
__device__ __forceinline__ uint32_t smem_to_u32(const void* p) {
    uint32_t a;
    asm("{ .reg .u64 t; cvta.to.shared.u64 t, %1; cvt.u32.u64 %0, t; }"
        : "=r"(a) : "l"(p));
    return a;
}

__device__ __forceinline__ void mma16816(float* d, const uint32_t* a,
                                         uint32_t b0, uint32_t b1) {
    asm volatile(
        "mma.sync.aligned.m16n8k16.row.col.f32.bf16.bf16.f32 "
        "{%0,%1,%2,%3}, {%4,%5,%6,%7}, {%8,%9}, {%0,%1,%2,%3};"
        : "+f"(d[0]), "+f"(d[1]), "+f"(d[2]), "+f"(d[3])
        : "r"(a[0]), "r"(a[1]), "r"(a[2]), "r"(a[3]),
          "r"(b0), "r"(b1));
}
__device__ __forceinline__ void mma16816h(float* d, const uint32_t* a,
                                          uint32_t b0, uint32_t b1) {
    asm volatile(
        "mma.sync.aligned.m16n8k16.row.col.f32.f16.f16.f32 "
        "{%0,%1,%2,%3}, {%4,%5,%6,%7}, {%8,%9}, {%0,%1,%2,%3};"
        : "+f"(d[0]), "+f"(d[1]), "+f"(d[2]), "+f"(d[3])
        : "r"(a[0]), "r"(a[1]), "r"(a[2]), "r"(a[3]),
          "r"(b0), "r"(b1));
}

#define LDSM_X4(r, addr) \
    asm volatile("ldmatrix.sync.aligned.m8n8.x4.shared.b16 {%0,%1,%2,%3}, [%4];" \
        : "=r"((r)[0]), "=r"((r)[1]), "=r"((r)[2]), "=r"((r)[3]) : "r"(addr))
#define LDSM_X4_T(r, addr) \
    asm volatile("ldmatrix.sync.aligned.m8n8.x4.trans.shared.b16 {%0,%1,%2,%3}, [%4];" \
        : "=r"((r)[0]), "=r"((r)[1]), "=r"((r)[2]), "=r"((r)[3]) : "r"(addr))

#define CP_ASYNC16(saddr, gptr) \
    asm volatile("cp.async.cg.shared.global [%0], [%1], 16;" \
        :: "r"(saddr), "l"(__cvta_generic_to_global(gptr)) : "memory")
#define CP_COMMIT() asm volatile("cp.async.commit_group;" ::: "memory")

__device__ __forceinline__ uint32_t pack_bf16x2(float lo, float hi) {
    uint32_t r;
    asm("cvt.rn.bf16x2.f32 %0, %1, %2;" : "=r"(r) : "f"(hi), "f"(lo));
    return r;
}
__device__ __forceinline__ uint32_t pack_f16x2(float lo, float hi) {
    __half2 h = __floats2half2_rn(lo, hi);
    return *reinterpret_cast<uint32_t*>(&h);
}
__device__ __forceinline__ void split2(float e0, float e1,
                                       uint32_t& hi, uint32_t& lo) {
    __nv_bfloat16 h0 = __float2bfloat16(e0);
    __nv_bfloat16 h1 = __float2bfloat16(e1);
    hi = (uint32_t)__bfloat16_as_ushort(h0) |
         ((uint32_t)__bfloat16_as_ushort(h1) << 16);
    lo = pack_bf16x2(e0 - __bfloat162float(h0), e1 - __bfloat162float(h1));
}
__device__ __forceinline__ float qmax4(float v) {
    v = fmaxf(v, __shfl_xor_sync(0xffffffffu, v, 1));
    v = fmaxf(v, __shfl_xor_sync(0xffffffffu, v, 2));
    return v;
}
__device__ __forceinline__ float qsum4(float v) {
    v += __shfl_xor_sync(0xffffffffu, v, 1);
    v += __shfl_xor_sync(0xffffffffu, v, 2);
    return v;
}

// ---------------------------------------------------------------------------
// QKV projection, tensorized bf16x3 (epilogue: q/k split bf16, v plain fp16)
// ---------------------------------------------------------------------------
#define GSTR 72
#define GE_XH 0
#define GE_XL (128*GSTR)
#define GE_WH (2*128*GSTR)
#define GE_WL (GE_WH + 64*GSTR)
#define GEMM_SMEM ((2*128 + 2*64) * GSTR * 2)   // 55296 B

__global__ __launch_bounds__(256, 2) void qkv_mma_kernel(
        const float* __restrict__ x, const float* __restrict__ w) {
    extern __shared__ __nv_bfloat16 gsm[];
    const uint32_t su = smem_to_u32(gsm);
    const int tid  = threadIdx.x;
    const int lane = tid & 31;
    const int warp = tid >> 5;
    const int g    = lane >> 2;
    const int tq   = lane & 3;
    const int lrow = lane & 15;
    const int lsel = lane >> 4;
    const int m0   = blockIdx.x * 128;
    const int n0   = blockIdx.y * 64;

    float acc[8][4];
#pragma unroll
    for (int nt = 0; nt < 8; nt++)
#pragma unroll
        for (int c = 0; c < 4; c++) acc[nt][c] = 0.f;

    float4 xr[8], wr[4];
#pragma unroll
    for (int r = 0; r < 8; r++) {
        int f4 = tid + 256 * r, row = f4 >> 4, c4 = (f4 & 15) << 2;
        xr[r] = *reinterpret_cast<const float4*>(x + (size_t)(m0 + row) * EMB + c4);
    }
#pragma unroll
    for (int r = 0; r < 4; r++) {
        int f4 = tid + 256 * r, row = f4 >> 4, c4 = (f4 & 15) << 2;
        wr[r] = *reinterpret_cast<const float4*>(w + (size_t)row * 192 + n0 + c4);
    }

#pragma unroll 1
    for (int kt = 0; kt < EMB / 64; kt++) {
#pragma unroll
        for (int r = 0; r < 8; r++) {
            int f4 = tid + 256 * r, row = f4 >> 4, c = (f4 & 15) << 2;
            uint32_t h0, l0, h1, l1;
            split2(xr[r].x, xr[r].y, h0, l0);
            split2(xr[r].z, xr[r].w, h1, l1);
            *reinterpret_cast<uint2*>(gsm + GE_XH + row * GSTR + c) = make_uint2(h0, h1);
            *reinterpret_cast<uint2*>(gsm + GE_XL + row * GSTR + c) = make_uint2(l0, l1);
        }
#pragma unroll
        for (int r = 0; r < 4; r++) {
            int f4 = tid + 256 * r, row = f4 >> 4, c = (f4 & 15) << 2;
            uint32_t h0, l0, h1, l1;
            split2(wr[r].x, wr[r].y, h0, l0);
            split2(wr[r].z, wr[r].w, h1, l1);
            *reinterpret_cast<uint2*>(gsm + GE_WH + row * GSTR + c) = make_uint2(h0, h1);
            *reinterpret_cast<uint2*>(gsm + GE_WL + row * GSTR + c) = make_uint2(l0, l1);
        }
        __syncthreads();

        if (kt + 1 < EMB / 64) {
            const int kb = (kt + 1) * 64;
#pragma unroll
            for (int r = 0; r < 8; r++) {
                int f4 = tid + 256 * r, row = f4 >> 4, c4 = (f4 & 15) << 2;
                xr[r] = *reinterpret_cast<const float4*>(
                    x + (size_t)(m0 + row) * EMB + kb + c4);
            }
#pragma unroll
            for (int r = 0; r < 4; r++) {
                int f4 = tid + 256 * r, row = f4 >> 4, c4 = (f4 & 15) << 2;
                wr[r] = *reinterpret_cast<const float4*>(
                    w + (size_t)(kb + row) * 192 + n0 + c4);
            }
        }

#pragma unroll
        for (int ks = 0; ks < 4; ks++) {
            const int acol = 16 * ks + 8 * lsel;
            uint32_t ah[4], al[4];
            LDSM_X4(ah, su + (uint32_t)(GE_XH + (warp * 16 + lrow) * GSTR + acol) * 2);
            LDSM_X4(al, su + (uint32_t)(GE_XL + (warp * 16 + lrow) * GSTR + acol) * 2);
            const int wrow = 16 * ks + lrow;
#pragma unroll
            for (int np = 0; np < 4; np++) {
                uint32_t bh[4], bl[4];
                const int wcol = 16 * np + 8 * lsel;
                LDSM_X4_T(bh, su + (uint32_t)(GE_WH + wrow * GSTR + wcol) * 2);
                LDSM_X4_T(bl, su + (uint32_t)(GE_WL + wrow * GSTR + wcol) * 2);
                mma16816(acc[2 * np],     ah, bh[0], bh[1]);
                mma16816(acc[2 * np],     ah, bl[0], bl[1]);
                mma16816(acc[2 * np],     al, bh[0], bh[1]);
                mma16816(acc[2 * np + 1], ah, bh[2], bh[3]);
                mma16816(acc[2 * np + 1], ah, bl[2], bl[3]);
                mma16816(acc[2 * np + 1], al, bh[2], bh[3]);
            }
        }
        __syncthreads();
    }

    const int ra = m0 + warp * 16 + g;
    if (blockIdx.y == 2) {
        // V: plain fp16
#pragma unroll
        for (int nt = 0; nt < 8; nt++) {
            const int c = 8 * nt + 2 * tq;
            *reinterpret_cast<uint32_t*>(g_vf + (size_t)ra * HD + c) =
                pack_f16x2(acc[nt][0], acc[nt][1]);
            *reinterpret_cast<uint32_t*>(g_vf + (size_t)(ra + 8) * HD + c) =
                pack_f16x2(acc[nt][2], acc[nt][3]);
        }
    } else {
        __nv_bfloat16 *oh, *ol;
        float scale = 1.f;
        if (blockIdx.y == 0) { oh = g_qh; ol = g_ql; scale = 0.125f; }
        else                 { oh = g_kh; ol = g_kl; }
#pragma unroll
        for (int nt = 0; nt < 8; nt++) {
            const int c = 8 * nt + 2 * tq;
            uint32_t hi, lo;
            split2(acc[nt][0] * scale, acc[nt][1] * scale, hi, lo);
            *reinterpret_cast<uint32_t*>(oh + (size_t)ra * HD + c) = hi;
            *reinterpret_cast<uint32_t*>(ol + (size_t)ra * HD + c) = lo;
            split2(acc[nt][2] * scale, acc[nt][3] * scale, hi, lo);
            *reinterpret_cast<uint32_t*>(oh + (size_t)(ra + 8) * HD + c) = hi;
            *reinterpret_cast<uint32_t*>(ol + (size_t)(ra + 8) * HD + c) = lo;
        }
    }
}

// ---------------------------------------------------------------------------
// Flash attention, split-KV. QK = bf16x3, PV = plain fp16 (1 mma).
// smem/stage: K_hi, K_lo (bf16) + V (fp16) = 3 tiles; 2 stages = 48 KB.
// ---------------------------------------------------------------------------
#define T64 (64*64)
#define E_KH(s) ((s)*3*T64)
#define E_KL(s) ((s)*3*T64 + T64)
#define E_VF(s) ((s)*3*T64 + 2*T64)
#define ATTN_SMEM (6*T64*2)         // 49152 bytes

#define SWZ(row, ch) ((row)*64 + (((ch) ^ ((row) & 7)) << 3))

__device__ __forceinline__ void tile_copy_async(
    uint32_t su, int eoff, const void* src, int tid) {
#pragma unroll
    for (int r = 0; r < 4; r++) {
        int c   = tid + 128 * r;
        int row = c >> 3;
        int ch  = c & 7;
        uint32_t sa = su + (uint32_t)(eoff + SWZ(row, ch)) * 2;
        CP_ASYNC16(sa, (const char*)src + (row * HD + ch * 8) * 2);
    }
}

__global__ __launch_bounds__(128, 3) void attn_mma_kernel() {
    extern __shared__ __nv_bfloat16 sm[];
    const uint32_t su = smem_to_u32(sm);
    const int tid  = threadIdx.x;
    const int lane = tid & 31;
    const int warp = tid >> 5;
    const int g    = lane >> 2;
    const int tq   = lane & 3;
    const int lrow = lane & 15;
    const int lsel = lane >> 4;
    const int b    = blockIdx.y;
    const int q0   = blockIdx.x * 64;
    const int spl  = blockIdx.z;
    const int r0   = warp * 16 + g;
    const int t0   = spl * KT_PER;

    const size_t tokbase = (size_t)b * SEQ;

    // ---- stage Q through smem once, keep fragments in registers ----
    {
        const __nv_bfloat16* qh = g_qh + (tokbase + q0) * HD;
        const __nv_bfloat16* ql = g_ql + (tokbase + q0) * HD;
#pragma unroll
        for (int r = 0; r < 8; r++) {
            int c   = tid + 128 * (r & 3);
            int row = c >> 3;
            int ch  = c & 7;
            const __nv_bfloat16* src = (r < 4 ? qh : ql) + row * HD + ch * 8;
            uint4 v = *reinterpret_cast<const uint4*>(src);
            *reinterpret_cast<uint4*>(sm + (r < 4 ? 0 : T64) + SWZ(row, ch)) = v;
        }
    }
    __syncthreads();
    uint32_t aH[4][4], aL[4][4];
#pragma unroll
    for (int ks = 0; ks < 4; ks++) {
        const int R  = warp * 16 + lrow;
        const int cb = 2 * ks + lsel;
        LDSM_X4(aH[ks], su + (uint32_t)(SWZ(R, cb)) * 2);
        LDSM_X4(aL[ks], su + (uint32_t)(T64 + SWZ(R, cb)) * 2);
    }
    __syncthreads();

    // ---- prologue: first tile of this split ----
    tile_copy_async(su, E_KH(0), g_kh + (tokbase + t0 * 64) * HD, tid);
    tile_copy_async(su, E_KL(0), g_kl + (tokbase + t0 * 64) * HD, tid);
    tile_copy_async(su, E_VF(0), g_vf + (tokbase + t0 * 64) * HD, tid);
    CP_COMMIT();

    float m_i[2] = {-1e30f, -1e30f};
    float l_i[2] = {0.f, 0.f};
    float oacc[8][4];
#pragma unroll
    for (int nt = 0; nt < 8; nt++)
#pragma unroll
        for (int c = 0; c < 4; c++) oacc[nt][c] = 0.f;

#pragma unroll 1
    for (int tt = 0; tt < KT_PER; tt++) {
        const int st = tt & 1;
        if (tt + 1 < KT_PER) {
            const size_t nb = (tokbase + (t0 + tt + 1) * 64) * HD;
            const int ns = (tt + 1) & 1;
            tile_copy_async(su, E_KH(ns), g_kh + nb, tid);
            tile_copy_async(su, E_KL(ns), g_kl + nb, tid);
            tile_copy_async(su, E_VF(ns), g_vf + nb, tid);
            CP_COMMIT();
            asm volatile("cp.async.wait_group 1;" ::: "memory");
        } else {
            asm volatile("cp.async.wait_group 0;" ::: "memory");
        }
        __syncthreads();

        // ---- S = Q K^T : bf16x3, np-pair interleaved ----
        float sacc[8][4];
#pragma unroll
        for (int nt = 0; nt < 8; nt++)
#pragma unroll
            for (int c = 0; c < 4; c++) sacc[nt][c] = 0.f;

#pragma unroll
        for (int ks = 0; ks < 4; ks++) {
            const int cb = 2 * ks + lsel;
#pragma unroll
            for (int npp = 0; npp < 2; npp++) {
                const int k0 = (2 * npp) * 16 + lrow;
                const int k1 = (2 * npp + 1) * 16 + lrow;
                uint32_t bh0[4], bh1[4], bl0[4], bl1[4];
                LDSM_X4(bh0, su + (uint32_t)(E_KH(st) + SWZ(k0, cb)) * 2);
                LDSM_X4(bh1, su + (uint32_t)(E_KH(st) + SWZ(k1, cb)) * 2);
                LDSM_X4(bl0, su + (uint32_t)(E_KL(st) + SWZ(k0, cb)) * 2);
                LDSM_X4(bl1, su + (uint32_t)(E_KL(st) + SWZ(k1, cb)) * 2);
                float* s0 = sacc[4 * npp + 0];
                float* s1 = sacc[4 * npp + 1];
                float* s2 = sacc[4 * npp + 2];
                float* s3 = sacc[4 * npp + 3];
                mma16816(s0, aH[ks], bh0[0], bh0[2]);
                mma16816(s1, aH[ks], bh0[1], bh0[3]);
                mma16816(s2, aH[ks], bh1[0], bh1[2]);
                mma16816(s3, aH[ks], bh1[1], bh1[3]);
                mma16816(s0, aH[ks], bl0[0], bl0[2]);
                mma16816(s1, aH[ks], bl0[1], bl0[3]);
                mma16816(s2, aH[ks], bl1[0], bl1[2]);
                mma16816(s3, aH[ks], bl1[1], bl1[3]);
                mma16816(s0, aL[ks], bh0[0], bh0[2]);
                mma16816(s1, aL[ks], bh0[1], bh0[3]);
                mma16816(s2, aL[ks], bh1[0], bh1[2]);
                mma16816(s3, aL[ks], bh1[1], bh1[3]);
            }
        }

        // ---- online softmax; P packed as fp16 ----
        float mx0 = sacc[0][0], mx1 = sacc[0][2];
#pragma unroll
        for (int nt = 0; nt < 8; nt++) {
            mx0 = fmaxf(mx0, fmaxf(sacc[nt][0], sacc[nt][1]));
            mx1 = fmaxf(mx1, fmaxf(sacc[nt][2], sacc[nt][3]));
        }
        mx0 = qmax4(mx0); mx1 = qmax4(mx1);
        float mn0 = fmaxf(m_i[0], mx0);
        float mn1 = fmaxf(m_i[1], mx1);
        float alpha0 = __expf(m_i[0] - mn0);
        float alpha1 = __expf(m_i[1] - mn1);
        m_i[0] = mn0; m_i[1] = mn1;

        float s0 = 0.f, s1 = 0.f;
        uint32_t ph[4][4];
#pragma unroll
        for (int nt = 0; nt < 8; nt++) {
            float p0 = __expf(sacc[nt][0] - mn0);
            float p1 = __expf(sacc[nt][1] - mn0);
            float p2 = __expf(sacc[nt][2] - mn1);
            float p3 = __expf(sacc[nt][3] - mn1);
            s0 += p0 + p1;  s1 += p2 + p3;
            int ks = nt >> 1, hi2 = (nt & 1) << 1;
            ph[ks][hi2 + 0] = pack_f16x2(p0, p1);
            ph[ks][hi2 + 1] = pack_f16x2(p2, p3);
        }
        s0 = qsum4(s0); s1 = qsum4(s1);
        l_i[0] = alpha0 * l_i[0] + s0;
        l_i[1] = alpha1 * l_i[1] + s1;

        // ---- rescale O, then O += P V (plain fp16, 1 mma) ----
#pragma unroll
        for (int nt = 0; nt < 8; nt++) {
            oacc[nt][0] *= alpha0; oacc[nt][1] *= alpha0;
            oacc[nt][2] *= alpha1; oacc[nt][3] *= alpha1;
        }
#pragma unroll
        for (int ks = 0; ks < 4; ks++) {
            const int vr = 16 * ks + lrow;
#pragma unroll
            for (int npp = 0; npp < 2; npp++) {
                const int cb0 = 2 * (2 * npp) + lsel;
                const int cb1 = 2 * (2 * npp + 1) + lsel;
                uint32_t vf0[4], vf1[4];
                LDSM_X4_T(vf0, su + (uint32_t)(E_VF(st) + SWZ(vr, cb0)) * 2);
                LDSM_X4_T(vf1, su + (uint32_t)(E_VF(st) + SWZ(vr, cb1)) * 2);
                mma16816h(oacc[4 * npp + 0], ph[ks], vf0[0], vf0[1]);
                mma16816h(oacc[4 * npp + 1], ph[ks], vf0[2], vf0[3]);
                mma16816h(oacc[4 * npp + 2], ph[ks], vf1[0], vf1[1]);
                mma16816h(oacc[4 * npp + 3], ph[ks], vf1[2], vf1[3]);
            }
        }
        __syncthreads();
    }

    // ---- epilogue: write unnormalized partial O + (m,l) ----
    const size_t row0 = tokbase + q0 + r0;
    float* po = g_po[spl];
#pragma unroll
    for (int nt = 0; nt < 8; nt++) {
        int col = 8 * nt + 2 * tq;
        *reinterpret_cast<float2*>(po + row0 * HD + col) =
            make_float2(oacc[nt][0], oacc[nt][1]);
        *reinterpret_cast<float2*>(po + (row0 + 8) * HD + col) =
            make_float2(oacc[nt][2], oacc[nt][3]);
    }
    if (tq == 0) {
        g_pm[spl][row0] = m_i[0];       g_pl[spl][row0] = l_i[0];
        g_pm[spl][row0 + 8] = m_i[1];   g_pl[spl][row0 + 8] = l_i[1];
    }
}

// ---------------------------------------------------------------------------
// Combine the NSPL partials
// ---------------------------------------------------------------------------
__global__ __launch_bounds__(256) void combine_kernel(float* __restrict__ out) {
    int idx = blockIdx.x * 256 + threadIdx.x;
    int row = idx >> 4;
    int c4  = (idx & 15) << 2;
    float m0 = g_pm[0][row], m1 = g_pm[1][row];
    float M  = fmaxf(m0, m1);
    float a0 = __expf(m0 - M), a1 = __expf(m1 - M);
    float inv = 1.f / (a0 * g_pl[0][row] + a1 * g_pl[1][row]);
    float4 o0 = *reinterpret_cast<const float4*>(g_po[0] + (size_t)row * HD + c4);
    float4 o1 = *reinterpret_cast<const float4*>(g_po[1] + (size_t)row * HD + c4);
    float4 r;
    r.x = (a0 * o0.x + a1 * o1.x) * inv;
    r.y = (a0 * o0.y + a1 * o1.y) * inv;
    r.z = (a0 * o0.z + a1 * o1.z) * inv;
    r.w = (a0 * o0.w + a1 * o1.w) * inv;
    *reinterpret_cast<float4*>(out + (size_t)row * HD + c4) = r;
}

// ---------------------------------------------------------------------------

extern "C" void kernel_launch(void* const* d_in, const int* in_sizes, int n_in,
                              void* d_out, int out_size) {
    (void)in_sizes; (void)n_in; (void)out_size;
    const float* x = (const float*)d_in[0];   // [4,4096,1024] fp32
    const float* w = (const float*)d_in[1];   // [1024,192]   fp32
    float* out = (float*)d_out;               // [4,4096,64]  fp32

    cudaFuncSetAttribute(qkv_mma_kernel,
                         cudaFuncAttributeMaxDynamicSharedMemorySize,
                         GEMM_SMEM);
    cudaFuncSetAttribute(attn_mma_kernel,
                         cudaFuncAttributeMaxDynamicSharedMemorySize,
                         ATTN_SMEM);

    qkv_mma_kernel<<<dim3(MT / 128, 3), 256, GEMM_SMEM>>>(x, w);
    attn_mma_kernel<<<dim3(SEQ / 64, BATCH, NSPL), 128, ATTN_SMEM>>>();
    combine_kernel<<<MT * HD / 4 / 256, 256>>>(out);
}

// round 9
// speedup vs baseline: 6.1330x; 1.3087x over previous
#include <cuda_runtime.h>
#include <cuda_bf16.h>
#include <cuda_fp16.h>
#include <cstdint>
#include <math.h>

#define BATCH 4
#define SEQ   4096
#define HD    64
#define EMB   1024
#define MT    (BATCH*SEQ)
#define NSPL  2
#define KT_PER (SEQ/64/NSPL)   // 32 k-tiles per split

// scratch written by GEMM epilogue (all fp16)
__device__ __align__(128) __half g_qh[MT*HD];   // q hi (scaled)
__device__ __align__(128) __half g_ql[MT*HD];   // q lo (scaled residual)
__device__ __align__(128) __half g_kf[MT*HD];   // k plain fp16
__device__ __align__(128) __half g_vf[MT*HD];   // v plain fp16

// split-KV partials
__device__ __align__(128) float g_po[NSPL][MT*HD];
__device__ float g_pm[NSPL][MT];
__device__ float g_pl[NSPL][MT];

// ---------------------------------------------------------------------------
// PTX helpers (baseline PTX only)
// ---------------------------------------------------------------------------
__device__ __forceinline__ uint32_t smem_to_u32(const void* p) {
    uint32_t a;
    asm("{ .reg .u64 t; cvta.to.shared.u64 t, %1; cvt.u32.u64 %0, t; }"
        : "=r"(a) : "l"(p));
    return a;
}

__device__ __forceinline__ void mma16816h(float* d, const uint32_t* a,
                                          uint32_t b0, uint32_t b1) {
    asm volatile(
        "mma.sync.aligned.m16n8k16.row.col.f32.f16.f16.f32 "
        "{%0,%1,%2,%3}, {%4,%5,%6,%7}, {%8,%9}, {%0,%1,%2,%3};"
        : "+f"(d[0]), "+f"(d[1]), "+f"(d[2]), "+f"(d[3])
        : "r"(a[0]), "r"(a[1]), "r"(a[2]), "r"(a[3]),
          "r"(b0), "r"(b1));
}

#define LDSM_X4(r, addr) \
    asm volatile("ldmatrix.sync.aligned.m8n8.x4.shared.b16 {%0,%1,%2,%3}, [%4];" \
        : "=r"((r)[0]), "=r"((r)[1]), "=r"((r)[2]), "=r"((r)[3]) : "r"(addr))
#define LDSM_X4_T(r, addr) \
    asm volatile("ldmatrix.sync.aligned.m8n8.x4.trans.shared.b16 {%0,%1,%2,%3}, [%4];" \
        : "=r"((r)[0]), "=r"((r)[1]), "=r"((r)[2]), "=r"((r)[3]) : "r"(addr))

#define CP_ASYNC16(saddr, gptr) \
    asm volatile("cp.async.cg.shared.global [%0], [%1], 16;" \
        :: "r"(saddr), "l"(__cvta_generic_to_global(gptr)) : "memory")
#define CP_COMMIT() asm volatile("cp.async.commit_group;" ::: "memory")

__device__ __forceinline__ uint32_t pack_f16x2(float lo, float hi) {
    __half2 h = __floats2half2_rn(lo, hi);
    return *reinterpret_cast<uint32_t*>(&h);
}
// fp16 split of a pair: hi = fp16(x), lo = fp16(x - hi)
__device__ __forceinline__ void split2h(float e0, float e1,
                                        uint32_t& hi, uint32_t& lo) {
    __half h0 = __float2half_rn(e0);
    __half h1 = __float2half_rn(e1);
    __half2 hh = __halves2half2(h0, h1);
    hi = *reinterpret_cast<uint32_t*>(&hh);
    lo = pack_f16x2(e0 - __half2float(h0), e1 - __half2float(h1));
}
__device__ __forceinline__ float qmax4(float v) {
    v = fmaxf(v, __shfl_xor_sync(0xffffffffu, v, 1));
    v = fmaxf(v, __shfl_xor_sync(0xffffffffu, v, 2));
    return v;
}
__device__ __forceinline__ float qsum4(float v) {
    v += __shfl_xor_sync(0xffffffffu, v, 1);
    v += __shfl_xor_sync(0xffffffffu, v, 2);
    return v;
}

// ---------------------------------------------------------------------------
// QKV projection: fp16x2 asymmetric split (X split, W plain) — 2 mma/step.
// ---------------------------------------------------------------------------
#define GSTR 72
#define GE_XH 0
#define GE_XL (128*GSTR)
#define GE_W  (2*128*GSTR)
#define GEMM_SMEM ((2*128 + 64) * GSTR * 2)   // 46080 B

__global__ __launch_bounds__(256, 2) void qkv_mma_kernel(
        const float* __restrict__ x, const float* __restrict__ w) {
    extern __shared__ __half gsm[];
    const uint32_t su = smem_to_u32(gsm);
    const int tid  = threadIdx.x;
    const int lane = tid & 31;
    const int warp = tid >> 5;
    const int g    = lane >> 2;
    const int tq   = lane & 3;
    const int lrow = lane & 15;
    const int lsel = lane >> 4;
    const int m0   = blockIdx.x * 128;
    const int n0   = blockIdx.y * 64;

    float acc[8][4];
#pragma unroll
    for (int nt = 0; nt < 8; nt++)
#pragma unroll
        for (int c = 0; c < 4; c++) acc[nt][c] = 0.f;

    float4 xr[8], wr[4];
#pragma unroll
    for (int r = 0; r < 8; r++) {
        int f4 = tid + 256 * r, row = f4 >> 4, c4 = (f4 & 15) << 2;
        xr[r] = *reinterpret_cast<const float4*>(x + (size_t)(m0 + row) * EMB + c4);
    }
#pragma unroll
    for (int r = 0; r < 4; r++) {
        int f4 = tid + 256 * r, row = f4 >> 4, c4 = (f4 & 15) << 2;
        wr[r] = *reinterpret_cast<const float4*>(w + (size_t)row * 192 + n0 + c4);
    }

#pragma unroll 1
    for (int kt = 0; kt < EMB / 64; kt++) {
        // ---- convert + store tiles: X split hi/lo, W plain ----
#pragma unroll
        for (int r = 0; r < 8; r++) {
            int f4 = tid + 256 * r, row = f4 >> 4, c = (f4 & 15) << 2;
            uint32_t h0, l0, h1, l1;
            split2h(xr[r].x, xr[r].y, h0, l0);
            split2h(xr[r].z, xr[r].w, h1, l1);
            *reinterpret_cast<uint2*>(gsm + GE_XH + row * GSTR + c) = make_uint2(h0, h1);
            *reinterpret_cast<uint2*>(gsm + GE_XL + row * GSTR + c) = make_uint2(l0, l1);
        }
#pragma unroll
        for (int r = 0; r < 4; r++) {
            int f4 = tid + 256 * r, row = f4 >> 4, c = (f4 & 15) << 2;
            *reinterpret_cast<uint2*>(gsm + GE_W + row * GSTR + c) =
                make_uint2(pack_f16x2(wr[r].x, wr[r].y),
                           pack_f16x2(wr[r].z, wr[r].w));
        }
        __syncthreads();

        // ---- prefetch next k-tile (hidden under mma) ----
        if (kt + 1 < EMB / 64) {
            const int kb = (kt + 1) * 64;
#pragma unroll
            for (int r = 0; r < 8; r++) {
                int f4 = tid + 256 * r, row = f4 >> 4, c4 = (f4 & 15) << 2;
                xr[r] = *reinterpret_cast<const float4*>(
                    x + (size_t)(m0 + row) * EMB + kb + c4);
            }
#pragma unroll
            for (int r = 0; r < 4; r++) {
                int f4 = tid + 256 * r, row = f4 >> 4, c4 = (f4 & 15) << 2;
                wr[r] = *reinterpret_cast<const float4*>(
                    w + (size_t)(kb + row) * 192 + n0 + c4);
            }
        }

        // ---- mma: 4 ksteps x 4 ntiles x (hi + lo) ----
#pragma unroll
        for (int ks = 0; ks < 4; ks++) {
            const int acol = 16 * ks + 8 * lsel;
            uint32_t ah[4], al[4];
            LDSM_X4(ah, su + (uint32_t)(GE_XH + (warp * 16 + lrow) * GSTR + acol) * 2);
            LDSM_X4(al, su + (uint32_t)(GE_XL + (warp * 16 + lrow) * GSTR + acol) * 2);
            const int wrow = 16 * ks + lrow;
#pragma unroll
            for (int np = 0; np < 4; np++) {
                uint32_t bh[4];
                const int wcol = 16 * np + 8 * lsel;
                LDSM_X4_T(bh, su + (uint32_t)(GE_W + wrow * GSTR + wcol) * 2);
                mma16816h(acc[2 * np],     ah, bh[0], bh[1]);
                mma16816h(acc[2 * np + 1], ah, bh[2], bh[3]);
                mma16816h(acc[2 * np],     al, bh[0], bh[1]);
                mma16816h(acc[2 * np + 1], al, bh[2], bh[3]);
            }
        }
        __syncthreads();
    }

    const int ra = m0 + warp * 16 + g;
    if (blockIdx.y == 0) {
        // Q: scaled + fp16-split
#pragma unroll
        for (int nt = 0; nt < 8; nt++) {
            const int c = 8 * nt + 2 * tq;
            uint32_t hi, lo;
            split2h(acc[nt][0] * 0.125f, acc[nt][1] * 0.125f, hi, lo);
            *reinterpret_cast<uint32_t*>(g_qh + (size_t)ra * HD + c) = hi;
            *reinterpret_cast<uint32_t*>(g_ql + (size_t)ra * HD + c) = lo;
            split2h(acc[nt][2] * 0.125f, acc[nt][3] * 0.125f, hi, lo);
            *reinterpret_cast<uint32_t*>(g_qh + (size_t)(ra + 8) * HD + c) = hi;
            *reinterpret_cast<uint32_t*>(g_ql + (size_t)(ra + 8) * HD + c) = lo;
        }
    } else {
        __half* dst = (blockIdx.y == 1) ? g_kf : g_vf;
#pragma unroll
        for (int nt = 0; nt < 8; nt++) {
            const int c = 8 * nt + 2 * tq;
            *reinterpret_cast<uint32_t*>(dst + (size_t)ra * HD + c) =
                pack_f16x2(acc[nt][0], acc[nt][1]);
            *reinterpret_cast<uint32_t*>(dst + (size_t)(ra + 8) * HD + c) =
                pack_f16x2(acc[nt][2], acc[nt][3]);
        }
    }
}

// ---------------------------------------------------------------------------
// Flash attention, split-KV. QK = q(fp16x2)·k(fp16) [2 mma], PV = fp16 [1 mma].
// smem/stage: K + V fp16 = 2 tiles; 2 stages = 32 KB.
// ---------------------------------------------------------------------------
#define T64 (64*64)
#define E_KF(s) ((s)*2*T64)
#define E_VF(s) ((s)*2*T64 + T64)
#define ATTN_SMEM (4*T64*2)         // 32768 bytes

#define SWZ(row, ch) ((row)*64 + (((ch) ^ ((row) & 7)) << 3))

__device__ __forceinline__ void tile_copy_async(
    uint32_t su, int eoff, const void* src, int tid) {
#pragma unroll
    for (int r = 0; r < 4; r++) {
        int c   = tid + 128 * r;
        int row = c >> 3;
        int ch  = c & 7;
        uint32_t sa = su + (uint32_t)(eoff + SWZ(row, ch)) * 2;
        CP_ASYNC16(sa, (const char*)src + (row * HD + ch * 8) * 2);
    }
}

__global__ __launch_bounds__(128, 3) void attn_mma_kernel() {
    extern __shared__ __half sm[];
    const uint32_t su = smem_to_u32(sm);
    const int tid  = threadIdx.x;
    const int lane = tid & 31;
    const int warp = tid >> 5;
    const int g    = lane >> 2;
    const int tq   = lane & 3;
    const int lrow = lane & 15;
    const int lsel = lane >> 4;
    const int b    = blockIdx.y;
    const int q0   = blockIdx.x * 64;
    const int spl  = blockIdx.z;
    const int r0   = warp * 16 + g;
    const int t0   = spl * KT_PER;

    const size_t tokbase = (size_t)b * SEQ;

    // ---- stage Q through smem once, keep fragments in registers ----
    {
        const __half* qh = g_qh + (tokbase + q0) * HD;
        const __half* ql = g_ql + (tokbase + q0) * HD;
#pragma unroll
        for (int r = 0; r < 8; r++) {
            int c   = tid + 128 * (r & 3);
            int row = c >> 3;
            int ch  = c & 7;
            const __half* src = (r < 4 ? qh : ql) + row * HD + ch * 8;
            uint4 v = *reinterpret_cast<const uint4*>(src);
            *reinterpret_cast<uint4*>(sm + (r < 4 ? 0 : T64) + SWZ(row, ch)) = v;
        }
    }
    __syncthreads();
    uint32_t aH[4][4], aL[4][4];
#pragma unroll
    for (int ks = 0; ks < 4; ks++) {
        const int R  = warp * 16 + lrow;
        const int cb = 2 * ks + lsel;
        LDSM_X4(aH[ks], su + (uint32_t)(SWZ(R, cb)) * 2);
        LDSM_X4(aL[ks], su + (uint32_t)(T64 + SWZ(R, cb)) * 2);
    }
    __syncthreads();

    // ---- prologue: first tile of this split ----
    tile_copy_async(su, E_KF(0), g_kf + (tokbase + t0 * 64) * HD, tid);
    tile_copy_async(su, E_VF(0), g_vf + (tokbase + t0 * 64) * HD, tid);
    CP_COMMIT();

    float m_i[2] = {-1e30f, -1e30f};
    float l_i[2] = {0.f, 0.f};
    float oacc[8][4];
#pragma unroll
    for (int nt = 0; nt < 8; nt++)
#pragma unroll
        for (int c = 0; c < 4; c++) oacc[nt][c] = 0.f;

#pragma unroll 1
    for (int tt = 0; tt < KT_PER; tt++) {
        const int st = tt & 1;
        if (tt + 1 < KT_PER) {
            const size_t nb = (tokbase + (t0 + tt + 1) * 64) * HD;
            const int ns = (tt + 1) & 1;
            tile_copy_async(su, E_KF(ns), g_kf + nb, tid);
            tile_copy_async(su, E_VF(ns), g_vf + nb, tid);
            CP_COMMIT();
            asm volatile("cp.async.wait_group 1;" ::: "memory");
        } else {
            asm volatile("cp.async.wait_group 0;" ::: "memory");
        }
        __syncthreads();

        // ---- S = Q K^T : q split (2 mma), k plain fp16 ----
        float sacc[8][4];
#pragma unroll
        for (int nt = 0; nt < 8; nt++)
#pragma unroll
            for (int c = 0; c < 4; c++) sacc[nt][c] = 0.f;

#pragma unroll
        for (int ks = 0; ks < 4; ks++) {
            const int cb = 2 * ks + lsel;
#pragma unroll
            for (int npp = 0; npp < 2; npp++) {
                const int k0 = (2 * npp) * 16 + lrow;
                const int k1 = (2 * npp + 1) * 16 + lrow;
                uint32_t kf0[4], kf1[4];
                LDSM_X4(kf0, su + (uint32_t)(E_KF(st) + SWZ(k0, cb)) * 2);
                LDSM_X4(kf1, su + (uint32_t)(E_KF(st) + SWZ(k1, cb)) * 2);
                float* s0 = sacc[4 * npp + 0];
                float* s1 = sacc[4 * npp + 1];
                float* s2 = sacc[4 * npp + 2];
                float* s3 = sacc[4 * npp + 3];
                mma16816h(s0, aH[ks], kf0[0], kf0[2]);
                mma16816h(s1, aH[ks], kf0[1], kf0[3]);
                mma16816h(s2, aH[ks], kf1[0], kf1[2]);
                mma16816h(s3, aH[ks], kf1[1], kf1[3]);
                mma16816h(s0, aL[ks], kf0[0], kf0[2]);
                mma16816h(s1, aL[ks], kf0[1], kf0[3]);
                mma16816h(s2, aL[ks], kf1[0], kf1[2]);
                mma16816h(s3, aL[ks], kf1[1], kf1[3]);
            }
        }

        // ---- online softmax; P packed as fp16 ----
        float mx0 = sacc[0][0], mx1 = sacc[0][2];
#pragma unroll
        for (int nt = 0; nt < 8; nt++) {
            mx0 = fmaxf(mx0, fmaxf(sacc[nt][0], sacc[nt][1]));
            mx1 = fmaxf(mx1, fmaxf(sacc[nt][2], sacc[nt][3]));
        }
        mx0 = qmax4(mx0); mx1 = qmax4(mx1);
        float mn0 = fmaxf(m_i[0], mx0);
        float mn1 = fmaxf(m_i[1], mx1);
        float alpha0 = __expf(m_i[0] - mn0);
        float alpha1 = __expf(m_i[1] - mn1);
        m_i[0] = mn0; m_i[1] = mn1;

        float s0 = 0.f, s1 = 0.f;
        uint32_t ph[4][4];
#pragma unroll
        for (int nt = 0; nt < 8; nt++) {
            float p0 = __expf(sacc[nt][0] - mn0);
            float p1 = __expf(sacc[nt][1] - mn0);
            float p2 = __expf(sacc[nt][2] - mn1);
            float p3 = __expf(sacc[nt][3] - mn1);
            s0 += p0 + p1;  s1 += p2 + p3;
            int ks = nt >> 1, hi2 = (nt & 1) << 1;
            ph[ks][hi2 + 0] = pack_f16x2(p0, p1);
            ph[ks][hi2 + 1] = pack_f16x2(p2, p3);
        }
        s0 = qsum4(s0); s1 = qsum4(s1);
        l_i[0] = alpha0 * l_i[0] + s0;
        l_i[1] = alpha1 * l_i[1] + s1;

        // ---- rescale O, then O += P V (plain fp16, 1 mma) ----
#pragma unroll
        for (int nt = 0; nt < 8; nt++) {
            oacc[nt][0] *= alpha0; oacc[nt][1] *= alpha0;
            oacc[nt][2] *= alpha1; oacc[nt][3] *= alpha1;
        }
#pragma unroll
        for (int ks = 0; ks < 4; ks++) {
            const int vr = 16 * ks + lrow;
#pragma unroll
            for (int npp = 0; npp < 2; npp++) {
                const int cb0 = 2 * (2 * npp) + lsel;
                const int cb1 = 2 * (2 * npp + 1) + lsel;
                uint32_t vf0[4], vf1[4];
                LDSM_X4_T(vf0, su + (uint32_t)(E_VF(st) + SWZ(vr, cb0)) * 2);
                LDSM_X4_T(vf1, su + (uint32_t)(E_VF(st) + SWZ(vr, cb1)) * 2);
                mma16816h(oacc[4 * npp + 0], ph[ks], vf0[0], vf0[1]);
                mma16816h(oacc[4 * npp + 1], ph[ks], vf0[2], vf0[3]);
                mma16816h(oacc[4 * npp + 2], ph[ks], vf1[0], vf1[1]);
                mma16816h(oacc[4 * npp + 3], ph[ks], vf1[2], vf1[3]);
            }
        }
        __syncthreads();
    }

    // ---- epilogue: write unnormalized partial O + (m,l) ----
    const size_t row0 = tokbase + q0 + r0;
    float* po = g_po[spl];
#pragma unroll
    for (int nt = 0; nt < 8; nt++) {
        int col = 8 * nt + 2 * tq;
        *reinterpret_cast<float2*>(po + row0 * HD + col) =
            make_float2(oacc[nt][0], oacc[nt][1]);
        *reinterpret_cast<float2*>(po + (row0 + 8) * HD + col) =
            make_float2(oacc[nt][2], oacc[nt][3]);
    }
    if (tq == 0) {
        g_pm[spl][row0] = m_i[0];       g_pl[spl][row0] = l_i[0];
        g_pm[spl][row0 + 8] = m_i[1];   g_pl[spl][row0 + 8] = l_i[1];
    }
}

// ---------------------------------------------------------------------------
// Combine the NSPL partials
// ---------------------------------------------------------------------------
__global__ __launch_bounds__(256) void combine_kernel(float* __restrict__ out) {
    int idx = blockIdx.x * 256 + threadIdx.x;
    int row = idx >> 4;
    int c4  = (idx & 15) << 2;
    float m0 = g_pm[0][row], m1 = g_pm[1][row];
    float M  = fmaxf(m0, m1);
    float a0 = __expf(m0 - M), a1 = __expf(m1 - M);
    float inv = 1.f / (a0 * g_pl[0][row] + a1 * g_pl[1][row]);
    float4 o0 = *reinterpret_cast<const float4*>(g_po[0] + (size_t)row * HD + c4);
    float4 o1 = *reinterpret_cast<const float4*>(g_po[1] + (size_t)row * HD + c4);
    float4 r;
    r.x = (a0 * o0.x + a1 * o1.x) * inv;
    r.y = (a0 * o0.y + a1 * o1.y) * inv;
    r.z = (a0 * o0.z + a1 * o1.z) * inv;
    r.w = (a0 * o0.w + a1 * o1.w) * inv;
    *reinterpret_cast<float4*>(out + (size_t)row * HD + c4) = r;
}

// ---------------------------------------------------------------------------

extern "C" void kernel_launch(void* const* d_in, const int* in_sizes, int n_in,
                              void* d_out, int out_size) {
    (void)in_sizes; (void)n_in; (void)out_size;
    const float* x = (const float*)d_in[0];   // [4,4096,1024] fp32
    const float* w = (const float*)d_in[1];   // [1024,192]   fp32
    float* out = (float*)d_out;               // [4,4096,64]  fp32

    cudaFuncSetAttribute(qkv_mma_kernel,
                         cudaFuncAttributeMaxDynamicSharedMemorySize,
                         GEMM_SMEM);
    cudaFuncSetAttribute(attn_mma_kernel,
                         cudaFuncAttributeMaxDynamicSharedMemorySize,
                         ATTN_SMEM);

    qkv_mma_kernel<<<dim3(MT / 128, 3), 256, GEMM_SMEM>>>(x, w);
    attn_mma_kernel<<<dim3(SEQ / 64, BATCH, NSPL), 128, ATTN_SMEM>>>();
    combine_kernel<<<MT * HD / 4 / 256, 256>>>(out);
}